// round 13
// baseline (speedup 1.0000x reference)
#include <cuda_runtime.h>
#include <cuda_fp16.h>
#include <cstdint>

#define BB 2048
#define NN 64
#define DD 512
#define HH 8
#define LL 3
#define FFD 2048
#define RR 400
#define EE 100000

// ---------------- device scratch ----------------
__device__ __align__(256) __half g_embeH[EE * 512];        // used-rows (compact) fp16 emb_e
__device__ __align__(256) __half g_eW2H[EE * 512];         // compact eW2 rows
__device__ __align__(256) __half g_embrH[RR * 512];
__device__ __align__(256) __half g_actH[2 * BB * 512];     // [0]=hH, [1]=embqH
__device__ __align__(256) __half g_ctxH[BB * HH * 512];
__device__ __align__(256) __half g_ffH[BB * 2048];
__device__ __align__(256) __half g_rW1H[RR * 512];
__device__ __align__(256) __half g_KhatH[LL * RR * 512];
__device__ __align__(256) __half g_W2h[512 * 512];
__device__ __align__(256) __half g_W1h[512 * 512];
__device__ __align__(256) __half g_Wcomb[LL * 2 * 512 * 512];  // [l][0]=W0, [l][1]=Wq[l]
__device__ __align__(256) __half g_Wkh[LL * 512 * 512];
__device__ __align__(256) __half g_Wvh[LL * 512 * 512];
__device__ __align__(256) __half g_F1h[LL * 2048 * 512];
__device__ __align__(256) __half g_F2h[LL * 512 * 2048];
__device__ __align__(256) float  g_bias2[LL * 1024];           // [l]: 512 zeros | bq[l]
__device__ __align__(256) float  g_h[BB * 512];
__device__ __align__(256) float  g_hw0qh[2 * BB * 512];        // [0]=hW0, [1]=qh
__device__ __align__(256) float  g_x[2 * BB * 512];
__device__ unsigned char g_flag[EE];
__device__ int g_cnt;
__device__ int g_list[EE];
__device__ int g_remap[EE];

// ---------------- helpers ----------------
__device__ __forceinline__ uint32_t s2u(const void* p) {
    uint32_t a;
    asm("{ .reg .u64 t; cvta.to.shared.u64 t, %1; cvt.u32.u64 %0, t; }" : "=r"(a) : "l"(p));
    return a;
}
__device__ __forceinline__ void cp16(uint32_t d, const void* s) {
    asm volatile("cp.async.cg.shared.global [%0], [%1], 16;" :: "r"(d), "l"(s));
}
__device__ __forceinline__ void cp_commit() { asm volatile("cp.async.commit_group;" ::: "memory"); }
template<int G> __device__ __forceinline__ void cp_wait() {
    asm volatile("cp.async.wait_group %0;" :: "n"(G) : "memory");
}
__device__ __forceinline__ void ldm4(uint32_t& r0, uint32_t& r1, uint32_t& r2, uint32_t& r3, uint32_t a) {
    asm volatile("ldmatrix.sync.aligned.m8n8.x4.shared.b16 {%0,%1,%2,%3}, [%4];"
        : "=r"(r0), "=r"(r1), "=r"(r2), "=r"(r3) : "r"(a));
}
__device__ __forceinline__ void mma_f16(float* c, const uint32_t* a, const uint32_t* b) {
    asm volatile(
        "mma.sync.aligned.m16n8k16.row.col.f32.f16.f16.f32 "
        "{%0,%1,%2,%3}, {%4,%5,%6,%7}, {%8,%9}, {%0,%1,%2,%3};"
        : "+f"(c[0]), "+f"(c[1]), "+f"(c[2]), "+f"(c[3])
        : "r"(a[0]), "r"(a[1]), "r"(a[2]), "r"(a[3]), "r"(b[0]), "r"(b[1]));
}
// SW128: 16B chunk swizzle within 128B rows
__device__ __forceinline__ uint32_t ofs128(int row, int c) {
    return (uint32_t)(row * 128 + ((c ^ (row & 7)) << 4));
}

// ---------------- fp16 HMMA GEMM, BK=64, 3-stage cp.async pipeline ----------------
template<int BN, int OUTH>
__global__ void __launch_bounds__(256, 2) gemm_f2(
    const __half* __restrict__ A, int a_ld, long long za,
    const int* __restrict__ gidx, int M,
    const __half* __restrict__ B, long long zb, int K,
    const float* __restrict__ bias, long long zbias,
    void* __restrict__ Cv, int ldc, int zn, long long zc,
    int kz, int kspan, int act, const int* __restrict__ Mdyn)
{
    constexpr int WARPS_N = BN / 32;
    constexpr int WARPS_M = 8 / WARPS_N;
    constexpr int WM = 128 / WARPS_M;
    constexpr int MAT_M = WM / 16;
    constexpr int STAGE = (128 + BN) * 128;
    constexpr int UNITS = (128 + BN) * 8;

    extern __shared__ __align__(1024) char smem[];
    int* s_idx = (int*)smem;
    const uint32_t sb = s2u(smem);
    const int tid = threadIdx.x, w = tid >> 5, lane = tid & 31;
    const int wm = w / WARPS_N, wn = w % WARPS_N;
    const int gm0 = blockIdx.y * 128;
    const int bn0 = blockIdx.x * BN;
    const int z = blockIdx.z;
    const int n0g = bn0 + z * zn;

    if (Mdyn) M = *Mdyn;
    if (gm0 >= M) return;

    A += (size_t)z * za;
    B += (size_t)z * zb;
    if (kz && z > 0) bias = nullptr;
    else if (bias) bias += (size_t)z * zbias;

    if (tid < 128) {
        int gr = gm0 + tid;
        if (gr >= M) gr = M - 1;
        s_idx[tid] = gidx ? gidx[gr] : gr;
    }
    __syncthreads();

    const int NCH = K >> 6;
    const int kbeg = kz ? z * kspan : 0;
    const int kcnt = kz ? kspan : NCH;

    auto load_chunk = [&](int c) {
        int s = c % 3;
        int koff = c * 64;
        uint32_t st = sb + 512 + s * STAGE;
#pragma unroll
        for (int it = 0; it < UNITS / 256; it++) {
            int u = tid + it * 256;
            if (u < 1024) {
                int r = u >> 3, c16 = u & 7;
                cp16(st + ofs128(r, c16),
                     A + (size_t)s_idx[r] * a_ld + koff + c16 * 8);
            } else {
                int v = u - 1024;
                int n = v >> 3, c16 = v & 7;
                cp16(st + 16384 + ofs128(n, c16),
                     B + (size_t)(bn0 + n) * K + koff + c16 * 8);
            }
        }
        cp_commit();
    };

    float acc[MAT_M][4][4];
#pragma unroll
    for (int i = 0; i < MAT_M; i++)
#pragma unroll
        for (int j = 0; j < 4; j++)
#pragma unroll
            for (int q = 0; q < 4; q++) acc[i][j][q] = 0.f;

    load_chunk(kbeg);
    load_chunk(kbeg + 1);

    const int r8 = lane & 7, sel = lane >> 3;

    for (int cc = 0; cc < kcnt; cc++) {
        int c = kbeg + cc;
        cp_wait<1>();
        __syncthreads();
        uint32_t stA = sb + 512 + (c % 3) * STAGE;
        uint32_t stB = stA + 16384;
#pragma unroll
        for (int kt = 0; kt < 4; kt++) {
            uint32_t a[MAT_M][4];
#pragma unroll
            for (int i = 0; i < MAT_M; i++) {
                int ar = wm * WM + i * 16 + r8 + (sel & 1) * 8;
                int ac = kt * 2 + (sel >> 1);
                ldm4(a[i][0], a[i][1], a[i][2], a[i][3], stA + ofs128(ar, ac));
            }
            uint32_t b[4][2];
#pragma unroll
            for (int p = 0; p < 2; p++) {
                int br = wn * 32 + p * 16 + r8 + (sel >> 1) * 8;
                int bc = kt * 2 + (sel & 1);
                uint32_t t0, t1, t2, t3;
                ldm4(t0, t1, t2, t3, stB + ofs128(br, bc));
                b[2 * p][0] = t0; b[2 * p][1] = t1;
                b[2 * p + 1][0] = t2; b[2 * p + 1][1] = t3;
            }
#pragma unroll
            for (int i = 0; i < MAT_M; i++)
#pragma unroll
                for (int j = 0; j < 4; j++)
                    mma_f16(acc[i][j], a[i], b[j]);
        }
        if (cc + 2 < kcnt) load_chunk(c + 2);
        else cp_commit();
    }

    const int g = lane >> 2, tig = lane & 3;
#pragma unroll
    for (int i = 0; i < MAT_M; i++) {
#pragma unroll
        for (int half = 0; half < 2; half++) {
            int m = gm0 + wm * WM + i * 16 + g + half * 8;
            if (m < M) {
#pragma unroll
                for (int j = 0; j < 4; j++) {
                    int nc = n0g + wn * 32 + j * 8 + tig * 2;
                    float v0 = acc[i][j][half * 2 + 0];
                    float v1 = acc[i][j][half * 2 + 1];
                    if (bias) { v0 += bias[nc]; v1 += bias[nc + 1]; }
                    if (act)  { v0 = fmaxf(v0, 0.f); v1 = fmaxf(v1, 0.f); }
                    if (OUTH) {
                        __half* Ch = (__half*)Cv + (size_t)z * zc;
                        *(__half2*)&Ch[(size_t)m * ldc + nc] = __floats2half2_rn(v0, v1);
                    } else {
                        float* Cf = (float*)Cv + (size_t)z * zc;
                        float2 o; o.x = v0; o.y = v1;
                        *(float2*)&Cf[(size_t)m * ldc + nc] = o;
                    }
                }
            }
        }
    }
}

// ---------------- compaction of used entity rows ----------------
__global__ void __launch_bounds__(256) zero_k(unsigned char* flag, int* cnt)
{
    int i = blockIdx.x * 256 + threadIdx.x;
    if (i < EE) flag[i] = 0;
    if (i == 0) *cnt = 0;
}
__global__ void __launch_bounds__(256) mark_k(const int* __restrict__ nbe, unsigned char* flag)
{
    int i = blockIdx.x * 256 + threadIdx.x;
    if (i < BB * NN) flag[nbe[i]] = 1;
}
__global__ void __launch_bounds__(256) compact_k(
    const unsigned char* __restrict__ flag, int* cnt, int* list, int* remap)
{
    int e = blockIdx.x * 256 + threadIdx.x;
    if (e < EE && flag[e]) {
        int p = atomicAdd(cnt, 1);
        list[p] = e;
        remap[e] = p;
    }
}
__global__ void __launch_bounds__(128) convGather_k(
    const float* __restrict__ emb_e, const int* __restrict__ list,
    const int* __restrict__ cnt, __half* __restrict__ dst)
{
    int n = *cnt;
    for (int row = blockIdx.x; row < n; row += gridDim.x) {
        const float* s = emb_e + (size_t)list[row] * 512;
        __half* d = dst + (size_t)row * 512;
        for (int j = threadIdx.x; j < 512; j += 128)
            d[j] = __float2half_rn(s[j]);
    }
}

// ---------------- coalesced transpose weight conversion ----------------
__global__ void __launch_bounds__(256) convT_k(
    const float* __restrict__ W, int str_k, int str_h, long long wmat,
    int K, __half* __restrict__ B2, long long bmat)
{
    __shared__ float t[64][66];
    W += (size_t)blockIdx.z * wmat;
    B2 += (size_t)blockIdx.z * bmat;
    const int k0 = blockIdx.x * 64, n0 = blockIdx.y * 64;
    const float* Wp = W + (size_t)(n0 >> 6) * str_h;
    const int c = threadIdx.x & 63;
    const int r0 = threadIdx.x >> 6;
#pragma unroll
    for (int i = 0; i < 16; i++) {
        int r = r0 + i * 4;
        t[c][r] = Wp[(size_t)(k0 + r) * str_k + c];
    }
    __syncthreads();
    const int ck = threadIdx.x & 31;
    const int rn0 = threadIdx.x >> 5;
#pragma unroll
    for (int i = 0; i < 8; i++) {
        int rn = rn0 + i * 8;
        float2 f = *(const float2*)&t[rn][ck * 2];
        *(__half2*)&B2[(size_t)(n0 + rn) * K + k0 + ck * 2] = __floats2half2_rn(f.x, f.y);
    }
}

__global__ void __launch_bounds__(128) convA_h(
    const float* __restrict__ src, __half* __restrict__ dst)
{
    size_t i = (size_t)blockIdx.x * 512 + threadIdx.x;
#pragma unroll
    for (int t = 0; t < 4; t++)
        dst[i + t * 128] = __float2half_rn(src[i + t * 128]);
}

__global__ void __launch_bounds__(256) biasfill_k(
    const float* __restrict__ bq, float* __restrict__ bias2)
{
    int l = blockIdx.x;
    for (int t = threadIdx.x; t < 1024; t += 256)
        bias2[l * 1024 + t] = (t < 512) ? 0.f : bq[l * 512 + t - 512];
}

// ---------------- fused attention v2: prefetch + half2 ----------------
__global__ void __launch_bounds__(256) attn_k(
    const float* __restrict__ qh, const __half* __restrict__ KhatH,
    const int* __restrict__ nbr_r, const int* __restrict__ nbr_e,
    const int* __restrict__ remap,
    const float* __restrict__ masks,
    const float* __restrict__ hW0, const __half* __restrict__ eW2,
    const __half* __restrict__ rW1H,
    __half* __restrict__ ctxH)
{
    const int b = blockIdx.x;
    const int tid = threadIdx.x;
    const int lane = tid & 31, w = tid >> 5;

    __shared__ float s_q[512];
    __shared__ float s_attn[HH * 64];
    __shared__ int   s_nbr[NN], s_nbe[NN], s_act[NN];
    __shared__ int   s_wc[2];
    __shared__ unsigned s_kb[2];
    __shared__ __align__(16) __half s_val[3][1024];   // [stage]: eW2 row | rW1 row

    s_q[tid]       = qh[(size_t)b * 512 + tid];
    s_q[tid + 256] = qh[(size_t)b * 512 + tid + 256];
    s_attn[tid] = -1e31f; s_attn[tid + 256] = -1e31f;
    if (tid < NN) {
        s_nbr[tid] = nbr_r[b * NN + tid];
        s_nbe[tid] = remap[nbr_e[b * NN + tid]];
    }
    if (w < 2) {
        bool keep = masks[b * NN + tid] > 0.5f;
        unsigned bal = __ballot_sync(0xffffffffu, keep);
        if (lane == 0) { s_wc[w] = __popc(bal); s_kb[w] = bal; }
    }
    __syncthreads();
    if (w < 2) {
        unsigned bal = s_kb[w];
        if ((bal >> lane) & 1u) {
            int rank = __popc(bal & ((1u << lane) - 1u)) + (w ? s_wc[0] : 0);
            s_act[rank] = tid;
        }
    }
    const int nact = s_wc[0] + s_wc[1];
    __syncthreads();

    // scores over active neighbors only (Khat fp16, half2 loads)
    {
        float q0 = s_q[w * 64 + 2 * lane], q1 = s_q[w * 64 + 2 * lane + 1];
        for (int idx = 0; idx < nact; idx++) {
            int n = s_act[idx];
            const __half* kr = KhatH + (size_t)s_nbr[n] * 512 + w * 64;
            float2 kf = __half22float2(*(const __half2*)&kr[2 * lane]);
            float p = q0 * kf.x + q1 * kf.y;
#pragma unroll
            for (int o = 16; o; o >>= 1) p += __shfl_xor_sync(0xffffffffu, p, o);
            if (lane == 0) s_attn[w * 64 + n] = p * 0.125f;
        }
    }
    __syncwarp();
    {
        float s0 = s_attn[w * 64 + lane], s1 = s_attn[w * 64 + lane + 32];
        float m = fmaxf(s0, s1);
#pragma unroll
        for (int o = 16; o; o >>= 1) m = fmaxf(m, __shfl_xor_sync(0xffffffffu, m, o));
        float e0 = expf(s0 - m), e1 = expf(s1 - m);
        float sum = e0 + e1;
#pragma unroll
        for (int o = 16; o; o >>= 1) sum += __shfl_xor_sync(0xffffffffu, sum, o);
        float inv = 1.f / sum;
        s_attn[w * 64 + lane]      = e0 * inv;
        s_attn[w * 64 + lane + 32] = e1 * inv;
    }
    __syncthreads();

    // value pass: 3-stage cp.async prefetch of (eW2 | rW1) rows
    auto prefetch = [&](int ii) {
        if (ii < nact && tid < 128) {
            int n = s_act[ii];
            int s = ii % 3;
            if (tid < 64)
                cp16(s2u(&s_val[s][tid * 8]), eW2 + (size_t)s_nbe[n] * 512 + tid * 8);
            else
                cp16(s2u(&s_val[s][512 + (tid - 64) * 8]),
                     rW1H + (size_t)s_nbr[n] * 512 + (tid - 64) * 8);
        }
        cp_commit();
    };
    prefetch(0); prefetch(1); prefetch(2);

    const float2 hw0v = *(const float2*)&hW0[(size_t)b * 512 + 2 * tid];
    float acc[HH][2];
#pragma unroll
    for (int hh = 0; hh < HH; hh++) { acc[hh][0] = 0.f; acc[hh][1] = 0.f; }

    for (int ii = 0; ii < nact; ii++) {
        cp_wait<2>();
        __syncthreads();
        int s = ii % 3, n = s_act[ii];
        float2 ev = __half22float2(*(const __half2*)&s_val[s][2 * tid]);
        float2 rv = __half22float2(*(const __half2*)&s_val[s][512 + 2 * tid]);
        float v0 = hw0v.x + ev.x + rv.x;
        float v1 = hw0v.y + ev.y + rv.y;
        v0 = (v0 > 0.f) ? v0 : 0.01f * v0;
        v1 = (v1 > 0.f) ? v1 : 0.01f * v1;
#pragma unroll
        for (int hh = 0; hh < HH; hh++) {
            float a = s_attn[hh * 64 + n];
            acc[hh][0] += a * v0;
            acc[hh][1] += a * v1;
        }
        __syncthreads();
        prefetch(ii + 3);
    }
#pragma unroll
    for (int hh = 0; hh < HH; hh++) {
        *(__half2*)&ctxH[((size_t)b * HH + hh) * 512 + 2 * tid] =
            __floats2half2_rn(acc[hh][0], acc[hh][1]);
    }
}

// ---------------- layernorm ----------------
__global__ void __launch_bounds__(128) ln_k(
    float* __restrict__ h, const float* __restrict__ x, const float* __restrict__ x2,
    const float* __restrict__ gamma, const float* __restrict__ beta,
    __half* __restrict__ hH)
{
    const int b = blockIdx.x, tid = threadIdx.x;
    __shared__ float sred[8];
    float4 hv = ((const float4*)(h + (size_t)b * 512))[tid];
    float4 xv = ((const float4*)(x + (size_t)b * 512))[tid];
    float v0 = hv.x + xv.x, v1 = hv.y + xv.y, v2 = hv.z + xv.z, v3 = hv.w + xv.w;
    if (x2) {
        float4 x2v = ((const float4*)(x2 + (size_t)b * 512))[tid];
        v0 += x2v.x; v1 += x2v.y; v2 += x2v.z; v3 += x2v.w;
    }

    float s = v0 + v1 + v2 + v3;
#pragma unroll
    for (int o = 16; o; o >>= 1) s += __shfl_xor_sync(0xffffffffu, s, o);
    if ((tid & 31) == 0) sred[tid >> 5] = s;
    __syncthreads();
    float mean = (sred[0] + sred[1] + sred[2] + sred[3]) * (1.f / 512.f);

    v0 -= mean; v1 -= mean; v2 -= mean; v3 -= mean;
    float sq = v0 * v0 + v1 * v1 + v2 * v2 + v3 * v3;
#pragma unroll
    for (int o = 16; o; o >>= 1) sq += __shfl_xor_sync(0xffffffffu, sq, o);
    if ((tid & 31) == 0) sred[4 + (tid >> 5)] = sq;
    __syncthreads();
    float var = (sred[4] + sred[5] + sred[6] + sred[7]) * (1.f / 512.f);
    float rstd = rsqrtf(var + 1e-5f);

    float4 g = ((const float4*)gamma)[tid];
    float4 be = ((const float4*)beta)[tid];
    float o0 = v0 * rstd * g.x + be.x;
    float o1 = v1 * rstd * g.y + be.y;
    float o2 = v2 * rstd * g.z + be.z;
    float o3 = v3 * rstd * g.w + be.w;
    float4 o; o.x = o0; o.y = o1; o.z = o2; o.w = o3;
    ((float4*)(h + (size_t)b * 512))[tid] = o;

    __half2* d = (__half2*)(hH + (size_t)b * 512 + tid * 4);
    d[0] = __floats2half2_rn(o0, o1);
    d[1] = __floats2half2_rn(o2, o3);
}

// ---------------- init ----------------
__global__ void __launch_bounds__(128) init_k(
    const int* __restrict__ e1, const int* __restrict__ qi,
    const float* __restrict__ emb_e, const float* __restrict__ emb_r,
    float* __restrict__ h, __half* __restrict__ actH,
    float* __restrict__ outq, int writeq)
{
    const int b = blockIdx.x, t = threadIdx.x;
    const float* se = emb_e + (size_t)e1[b] * 512;
    const float* sr = emb_r + (size_t)qi[b] * 512;
    for (int j = t; j < 512; j += 128) {
        float hv = se[j];
        h[(size_t)b * 512 + j] = hv;
        actH[(size_t)b * 512 + j] = __float2half_rn(hv);
        float q = sr[j];
        actH[(size_t)(BB + b) * 512 + j] = __float2half_rn(q);
        if (writeq) outq[(size_t)b * 512 + j] = q;
    }
}

__global__ void copy_k(float* __restrict__ out, const float* __restrict__ in)
{
    int i = blockIdx.x * 256 + threadIdx.x;
    out[i] = in[i];
}

// ---------------- launch ----------------
extern "C" void kernel_launch(void* const* d_in, const int* in_sizes, int n_in,
                              void* d_out, int out_size)
{
    const int*   e1    = (const int*)d_in[0];
    const int*   qidx  = (const int*)d_in[1];
    const int*   nbr_r = (const int*)d_in[2];
    const int*   nbr_e = (const int*)d_in[3];
    const float* masks = (const float*)d_in[4];
    const float* emb_e = (const float*)d_in[5];
    const float* emb_r = (const float*)d_in[6];
    const float* msg_W = (const float*)d_in[7];
    const float* msg_b = (const float*)d_in[8];
    const float* Wq    = (const float*)d_in[9];
    const float* bq    = (const float*)d_in[10];
    const float* Wk    = (const float*)d_in[11];
    const float* bk    = (const float*)d_in[12];
    const float* Wv    = (const float*)d_in[13];
    const float* bv    = (const float*)d_in[14];
    const float* ffW1  = (const float*)d_in[15];
    const float* ffb1  = (const float*)d_in[16];
    const float* ffW2  = (const float*)d_in[17];
    const float* ffb2  = (const float*)d_in[18];
    const float* ln1g  = (const float*)d_in[19];
    const float* ln1b  = (const float*)d_in[20];
    const float* ln2g  = (const float*)d_in[21];
    const float* ln2b  = (const float*)d_in[22];
    float* out = (float*)d_out;

    __half *p_embeH, *p_eW2H, *p_embrH, *p_actH, *p_ctxH, *p_ffH, *p_rW1H, *p_KhatH;
    __half *p_W2h, *p_W1h, *p_Wcomb, *p_Wkh, *p_Wvh, *p_F1h, *p_F2h;
    float *p_bias2, *p_h, *p_hw0qh, *p_x;
    unsigned char* p_flag; int *p_cnt, *p_list, *p_remap;
    cudaGetSymbolAddress((void**)&p_embeH, g_embeH);
    cudaGetSymbolAddress((void**)&p_eW2H,  g_eW2H);
    cudaGetSymbolAddress((void**)&p_embrH, g_embrH);
    cudaGetSymbolAddress((void**)&p_actH,  g_actH);
    cudaGetSymbolAddress((void**)&p_ctxH,  g_ctxH);
    cudaGetSymbolAddress((void**)&p_ffH,   g_ffH);
    cudaGetSymbolAddress((void**)&p_rW1H,  g_rW1H);
    cudaGetSymbolAddress((void**)&p_KhatH, g_KhatH);
    cudaGetSymbolAddress((void**)&p_W2h,   g_W2h);
    cudaGetSymbolAddress((void**)&p_W1h,   g_W1h);
    cudaGetSymbolAddress((void**)&p_Wcomb, g_Wcomb);
    cudaGetSymbolAddress((void**)&p_Wkh,   g_Wkh);
    cudaGetSymbolAddress((void**)&p_Wvh,   g_Wvh);
    cudaGetSymbolAddress((void**)&p_F1h,   g_F1h);
    cudaGetSymbolAddress((void**)&p_F2h,   g_F2h);
    cudaGetSymbolAddress((void**)&p_bias2, g_bias2);
    cudaGetSymbolAddress((void**)&p_h,     g_h);
    cudaGetSymbolAddress((void**)&p_hw0qh, g_hw0qh);
    cudaGetSymbolAddress((void**)&p_x,     g_x);
    cudaGetSymbolAddress((void**)&p_flag,  g_flag);
    cudaGetSymbolAddress((void**)&p_cnt,   g_cnt);
    cudaGetSymbolAddress((void**)&p_list,  g_list);
    cudaGetSymbolAddress((void**)&p_remap, g_remap);

    const int SMK_128 = 512 + 3 * ((128 + 128) * 128);  // 98816
    const int SMK_64  = 512 + 3 * ((128 + 64) * 128);   // 74240
    cudaFuncSetAttribute((gemm_f2<128, 0>), cudaFuncAttributeMaxDynamicSharedMemorySize, SMK_128);
    cudaFuncSetAttribute((gemm_f2<128, 1>), cudaFuncAttributeMaxDynamicSharedMemorySize, SMK_128);
    cudaFuncSetAttribute((gemm_f2<64, 0>),  cudaFuncAttributeMaxDynamicSharedMemorySize, SMK_64);

    int writeq = (out_size >= 2 * BB * DD) ? 1 : 0;

    // used-row compaction (launches 1-4)
    zero_k<<<(EE + 255) / 256, 256>>>(p_flag, p_cnt);
    mark_k<<<(BB * NN + 255) / 256, 256>>>(nbr_e, p_flag);
    compact_k<<<(EE + 255) / 256, 256>>>(p_flag, p_cnt, p_list, p_remap);
    convGather_k<<<782, 128>>>(emb_e, p_list, p_cnt, p_embeH);
    // launch 5: W2 conversion
    convT_k<<<dim3(8, 8, 1), 256>>>(msg_W + 1024 * 512, 512, 64, 0, 512, p_W2h, 0);
    // launch 6 (profiled): eW2 = used_rows(emb_e) @ W2 + msg_b (compact M)
    gemm_f2<128, 1><<<dim3(4, (EE + 127) / 128), 256, SMK_128>>>(
        p_embeH, 512, 0, nullptr, EE, p_W2h, 0, 512,
        msg_b, 0, p_eW2H, 512, 0, 0, 0, 0, 0, p_cnt);

    init_k<<<BB, 128>>>(e1, qidx, emb_e, emb_r, p_h, p_actH, out + (size_t)BB * DD, writeq);
    convT_k<<<dim3(8, 8, 1), 256>>>(msg_W + 512 * 512, 512, 64, 0, 512, p_W1h, 0);
    convA_h<<<RR, 128>>>(emb_r, p_embrH);
    biasfill_k<<<LL, 256>>>(bq, p_bias2);
    convT_k<<<dim3(8, 8, LL), 256>>>(msg_W, 512, 64, 0, 512, p_Wcomb, 524288);
    convT_k<<<dim3(8, 8, LL), 256>>>(Wq, 64, 32768, 262144, 512, p_Wcomb + 262144, 524288);
    convT_k<<<dim3(8, 8, LL), 256>>>(Wk, 64, 32768, 262144, 512, p_Wkh, 262144);
    convT_k<<<dim3(8, 8, LL), 256>>>(Wv, 64, 32768, 262144, 512, p_Wvh, 262144);
    convT_k<<<dim3(8, 32, LL), 256>>>(ffW1, 2048, 64, 1048576, 512, p_F1h, 1048576);
    convT_k<<<dim3(32, 8, LL), 256>>>(ffW2, 512, 64, 1048576, 2048, p_F2h, 1048576);

    // rW1H = half(emb_r @ W1)
    gemm_f2<128, 1><<<dim3(4, 4), 256, SMK_128>>>(
        p_embrH, 512, 0, nullptr, RR, p_W1h, 0, 512,
        nullptr, 0, p_rW1H, 512, 0, 0, 0, 0, 0, nullptr);
    // KhatH[l] = half(emb_r @ Wk[l] + bk[l])
    gemm_f2<128, 1><<<dim3(4, 4, LL), 256, SMK_128>>>(
        p_embrH, 512, 0, nullptr, RR, p_Wkh, 262144, 512,
        bk, 512, p_KhatH, 512, 0, (long long)RR * 512, 0, 0, 0, nullptr);

    for (int l = 0; l < LL; l++) {
        // z=0: hW0 = h @ W0; z=1: qh = embq @ Wq[l] + bq[l]
        gemm_f2<128, 0><<<dim3(4, 16, 2), 256, SMK_128>>>(
            p_actH, 512, (long long)BB * 512, nullptr, BB,
            p_Wcomb + (size_t)l * 2 * 262144, 262144, 512,
            p_bias2 + l * 1024, 512,
            p_hw0qh, 512, 0, (long long)BB * 512, 0, 0, 0, nullptr);
        attn_k<<<BB, 256>>>(p_hw0qh + (size_t)BB * 512, p_KhatH + (size_t)l * RR * 512,
                            nbr_r, nbr_e, p_remap, masks, p_hw0qh, p_eW2H, p_rW1H, p_ctxH);
        // x = ctx @ Wv[l] + bv[l] (z = head)
        gemm_f2<64, 0><<<dim3(1, 16, 8), 256, SMK_64>>>(
            p_ctxH, 4096, 512, nullptr, BB,
            p_Wvh + (size_t)l * 262144, 32768, 512,
            bv + l * 512, 0, p_x, 512, 64, 0, 0, 0, 0, nullptr);
        ln_k<<<BB, 128>>>(p_h, p_x, nullptr, ln1g + l * 512, ln1b + l * 512, p_actH);
        // ffH = fp16(relu(h @ F1 + b1))
        gemm_f2<128, 1><<<dim3(16, 16), 256, SMK_128>>>(
            p_actH, 512, 0, nullptr, BB,
            p_F1h + (size_t)l * 1048576, 0, 512,
            ffb1 + l * 2048, 0, p_ffH, 2048, 0, 0, 0, 0, 1, nullptr);
        // x0/x1 = split-K halves of ff @ F2 (+ b2 on z=0)
        gemm_f2<128, 0><<<dim3(4, 16, 2), 256, SMK_128>>>(
            p_ffH, 2048, 0, nullptr, BB,
            p_F2h + (size_t)l * 1048576, 0, 2048,
            ffb2 + l * 512, 0, p_x, 512, 0, (long long)BB * 512, 1, 16, 0, nullptr);
        ln_k<<<BB, 128>>>(p_h, p_x, p_x + (size_t)BB * 512, ln2g + l * 512, ln2b + l * 512, p_actH);
    }

    copy_k<<<(BB * DD) / 256, 256>>>(out, p_h);
}

// round 15
// speedup vs baseline: 1.1460x; 1.1460x over previous
#include <cuda_runtime.h>
#include <cuda_fp16.h>
#include <cstdint>

#define BB 2048
#define NN 64
#define DD 512
#define HH 8
#define LL 3
#define FFD 2048
#define RR 400
#define EE 100000

// ---------------- device scratch ----------------
__device__ __align__(256) __half g_embeH[EE * 512];        // used-rows (compact) fp16 emb_e
__device__ __align__(256) __half g_eW2H[EE * 512];         // compact eW2 rows
__device__ __align__(256) __half g_embrH[RR * 512];
__device__ __align__(256) __half g_actH[2 * BB * 512];     // [0]=hH, [1]=embqH
__device__ __align__(256) __half g_ctxH[BB * HH * 512];
__device__ __align__(256) __half g_ffH[BB * 2048];
__device__ __align__(256) __half g_rW1H[RR * 512];
__device__ __align__(256) __half g_KhatH[LL * RR * 512];
__device__ __align__(256) __half g_W2h[512 * 512];
__device__ __align__(256) __half g_W1h[512 * 512];
__device__ __align__(256) __half g_Wcomb[LL * 2 * 512 * 512];  // [l][0]=W0, [l][1]=Wq[l]
__device__ __align__(256) __half g_Wkh[LL * 512 * 512];
__device__ __align__(256) __half g_Wvh[LL * 512 * 512];
__device__ __align__(256) __half g_F1h[LL * 2048 * 512];
__device__ __align__(256) __half g_F2h[LL * 512 * 2048];
__device__ __align__(256) float  g_bias2[LL * 1024];           // [l]: 512 zeros | bq[l]
__device__ __align__(256) float  g_h[BB * 512];
__device__ __align__(256) float  g_hw0qh[2 * BB * 512];        // [0]=hW0, [1]=qh
__device__ __align__(256) float  g_x[2 * BB * 512];
__device__ unsigned char g_flag[EE];
__device__ int g_cnt;
__device__ int g_list[EE];
__device__ int g_remap[EE];

// ---------------- helpers ----------------
__device__ __forceinline__ uint32_t s2u(const void* p) {
    uint32_t a;
    asm("{ .reg .u64 t; cvta.to.shared.u64 t, %1; cvt.u32.u64 %0, t; }" : "=r"(a) : "l"(p));
    return a;
}
__device__ __forceinline__ void cp16(uint32_t d, const void* s) {
    asm volatile("cp.async.cg.shared.global [%0], [%1], 16;" :: "r"(d), "l"(s));
}
__device__ __forceinline__ void cp_commit() { asm volatile("cp.async.commit_group;" ::: "memory"); }
template<int G> __device__ __forceinline__ void cp_wait() {
    asm volatile("cp.async.wait_group %0;" :: "n"(G) : "memory");
}
__device__ __forceinline__ void ldm4(uint32_t& r0, uint32_t& r1, uint32_t& r2, uint32_t& r3, uint32_t a) {
    asm volatile("ldmatrix.sync.aligned.m8n8.x4.shared.b16 {%0,%1,%2,%3}, [%4];"
        : "=r"(r0), "=r"(r1), "=r"(r2), "=r"(r3) : "r"(a));
}
__device__ __forceinline__ void mma_f16(float* c, const uint32_t* a, const uint32_t* b) {
    asm volatile(
        "mma.sync.aligned.m16n8k16.row.col.f32.f16.f16.f32 "
        "{%0,%1,%2,%3}, {%4,%5,%6,%7}, {%8,%9}, {%0,%1,%2,%3};"
        : "+f"(c[0]), "+f"(c[1]), "+f"(c[2]), "+f"(c[3])
        : "r"(a[0]), "r"(a[1]), "r"(a[2]), "r"(a[3]), "r"(b[0]), "r"(b[1]));
}
// SW128: 16B chunk swizzle within 128B rows
__device__ __forceinline__ uint32_t ofs128(int row, int c) {
    return (uint32_t)(row * 128 + ((c ^ (row & 7)) << 4));
}

// ---------------- fp16 HMMA GEMM, BK=64, 3-stage cp.async pipeline ----------------
template<int BN, int OUTH>
__global__ void __launch_bounds__(256, 2) gemm_f2(
    const __half* __restrict__ A, int a_ld, long long za,
    const int* __restrict__ gidx, int M,
    const __half* __restrict__ B, long long zb, int K,
    const float* __restrict__ bias, long long zbias,
    void* __restrict__ Cv, int ldc, int zn, long long zc,
    int kz, int kspan, int act, const int* __restrict__ Mdyn)
{
    constexpr int WARPS_N = BN / 32;
    constexpr int WARPS_M = 8 / WARPS_N;
    constexpr int WM = 128 / WARPS_M;
    constexpr int MAT_M = WM / 16;
    constexpr int STAGE = (128 + BN) * 128;
    constexpr int UNITS = (128 + BN) * 8;

    extern __shared__ __align__(1024) char smem[];
    int* s_idx = (int*)smem;
    const uint32_t sb = s2u(smem);
    const int tid = threadIdx.x, w = tid >> 5, lane = tid & 31;
    const int wm = w / WARPS_N, wn = w % WARPS_N;
    const int gm0 = blockIdx.y * 128;
    const int bn0 = blockIdx.x * BN;
    const int z = blockIdx.z;
    const int n0g = bn0 + z * zn;

    if (Mdyn) M = *Mdyn;
    if (gm0 >= M) return;

    A += (size_t)z * za;
    B += (size_t)z * zb;
    if (kz && z > 0) bias = nullptr;
    else if (bias) bias += (size_t)z * zbias;

    if (tid < 128) {
        int gr = gm0 + tid;
        if (gr >= M) gr = M - 1;
        s_idx[tid] = gidx ? gidx[gr] : gr;
    }
    __syncthreads();

    const int NCH = K >> 6;
    const int kbeg = kz ? z * kspan : 0;
    const int kcnt = kz ? kspan : NCH;

    auto load_chunk = [&](int c) {
        int s = c % 3;
        int koff = c * 64;
        uint32_t st = sb + 512 + s * STAGE;
#pragma unroll
        for (int it = 0; it < UNITS / 256; it++) {
            int u = tid + it * 256;
            if (u < 1024) {
                int r = u >> 3, c16 = u & 7;
                cp16(st + ofs128(r, c16),
                     A + (size_t)s_idx[r] * a_ld + koff + c16 * 8);
            } else {
                int v = u - 1024;
                int n = v >> 3, c16 = v & 7;
                cp16(st + 16384 + ofs128(n, c16),
                     B + (size_t)(bn0 + n) * K + koff + c16 * 8);
            }
        }
        cp_commit();
    };

    float acc[MAT_M][4][4];
#pragma unroll
    for (int i = 0; i < MAT_M; i++)
#pragma unroll
        for (int j = 0; j < 4; j++)
#pragma unroll
            for (int q = 0; q < 4; q++) acc[i][j][q] = 0.f;

    load_chunk(kbeg);
    load_chunk(kbeg + 1);

    const int r8 = lane & 7, sel = lane >> 3;

    for (int cc = 0; cc < kcnt; cc++) {
        int c = kbeg + cc;
        cp_wait<1>();
        __syncthreads();
        uint32_t stA = sb + 512 + (c % 3) * STAGE;
        uint32_t stB = stA + 16384;
#pragma unroll
        for (int kt = 0; kt < 4; kt++) {
            uint32_t a[MAT_M][4];
#pragma unroll
            for (int i = 0; i < MAT_M; i++) {
                int ar = wm * WM + i * 16 + r8 + (sel & 1) * 8;
                int ac = kt * 2 + (sel >> 1);
                ldm4(a[i][0], a[i][1], a[i][2], a[i][3], stA + ofs128(ar, ac));
            }
            uint32_t b[4][2];
#pragma unroll
            for (int p = 0; p < 2; p++) {
                int br = wn * 32 + p * 16 + r8 + (sel >> 1) * 8;
                int bc = kt * 2 + (sel & 1);
                uint32_t t0, t1, t2, t3;
                ldm4(t0, t1, t2, t3, stB + ofs128(br, bc));
                b[2 * p][0] = t0; b[2 * p][1] = t1;
                b[2 * p + 1][0] = t2; b[2 * p + 1][1] = t3;
            }
#pragma unroll
            for (int i = 0; i < MAT_M; i++)
#pragma unroll
                for (int j = 0; j < 4; j++)
                    mma_f16(acc[i][j], a[i], b[j]);
        }
        if (cc + 2 < kcnt) load_chunk(c + 2);
        else cp_commit();
    }

    const int g = lane >> 2, tig = lane & 3;
#pragma unroll
    for (int i = 0; i < MAT_M; i++) {
#pragma unroll
        for (int half = 0; half < 2; half++) {
            int m = gm0 + wm * WM + i * 16 + g + half * 8;
            if (m < M) {
#pragma unroll
                for (int j = 0; j < 4; j++) {
                    int nc = n0g + wn * 32 + j * 8 + tig * 2;
                    float v0 = acc[i][j][half * 2 + 0];
                    float v1 = acc[i][j][half * 2 + 1];
                    if (bias) { v0 += bias[nc]; v1 += bias[nc + 1]; }
                    if (act)  { v0 = fmaxf(v0, 0.f); v1 = fmaxf(v1, 0.f); }
                    if (OUTH) {
                        __half* Ch = (__half*)Cv + (size_t)z * zc;
                        *(__half2*)&Ch[(size_t)m * ldc + nc] = __floats2half2_rn(v0, v1);
                    } else {
                        float* Cf = (float*)Cv + (size_t)z * zc;
                        float2 o; o.x = v0; o.y = v1;
                        *(float2*)&Cf[(size_t)m * ldc + nc] = o;
                    }
                }
            }
        }
    }
}

// ---------------- compaction of used entity rows ----------------
__global__ void __launch_bounds__(256) zero_k(unsigned char* flag, int* cnt)
{
    int i = blockIdx.x * 256 + threadIdx.x;
    if (i < EE) flag[i] = 0;
    if (i == 0) *cnt = 0;
}
__global__ void __launch_bounds__(256) mark_k(const int* __restrict__ nbe, unsigned char* flag)
{
    int i = blockIdx.x * 256 + threadIdx.x;
    if (i < BB * NN) flag[nbe[i]] = 1;
}
__global__ void __launch_bounds__(256) compact_k(
    const unsigned char* __restrict__ flag, int* cnt, int* list, int* remap)
{
    int e = blockIdx.x * 256 + threadIdx.x;
    if (e < EE && flag[e]) {
        int p = atomicAdd(cnt, 1);
        list[p] = e;
        remap[e] = p;
    }
}
// one block per compact row: fully coalesced float4 gather + half2 store
__global__ void __launch_bounds__(128) convGather_k(
    const float* __restrict__ emb_e, const int* __restrict__ list,
    const int* __restrict__ cnt, __half* __restrict__ dst)
{
    int row = blockIdx.x;
    if (row >= *cnt) return;
    const float4* s = (const float4*)(emb_e + (size_t)list[row] * 512);
    float4 v = s[threadIdx.x];
    __half2 a = __floats2half2_rn(v.x, v.y);
    __half2 b = __floats2half2_rn(v.z, v.w);
    uint2 o;
    o.x = *(uint32_t*)&a;
    o.y = *(uint32_t*)&b;
    *(uint2*)(dst + (size_t)row * 512 + threadIdx.x * 4) = o;
}

// ---------------- coalesced transpose weight conversion ----------------
__global__ void __launch_bounds__(256) convT_k(
    const float* __restrict__ W, int str_k, int str_h, long long wmat,
    int K, __half* __restrict__ B2, long long bmat)
{
    __shared__ float t[64][66];
    W += (size_t)blockIdx.z * wmat;
    B2 += (size_t)blockIdx.z * bmat;
    const int k0 = blockIdx.x * 64, n0 = blockIdx.y * 64;
    const float* Wp = W + (size_t)(n0 >> 6) * str_h;
    const int c = threadIdx.x & 63;
    const int r0 = threadIdx.x >> 6;
#pragma unroll
    for (int i = 0; i < 16; i++) {
        int r = r0 + i * 4;
        t[c][r] = Wp[(size_t)(k0 + r) * str_k + c];
    }
    __syncthreads();
    const int ck = threadIdx.x & 31;
    const int rn0 = threadIdx.x >> 5;
#pragma unroll
    for (int i = 0; i < 8; i++) {
        int rn = rn0 + i * 8;
        float2 f = *(const float2*)&t[rn][ck * 2];
        *(__half2*)&B2[(size_t)(n0 + rn) * K + k0 + ck * 2] = __floats2half2_rn(f.x, f.y);
    }
}

__global__ void __launch_bounds__(128) convA_h(
    const float* __restrict__ src, __half* __restrict__ dst)
{
    size_t i = (size_t)blockIdx.x * 512 + threadIdx.x;
#pragma unroll
    for (int t = 0; t < 4; t++)
        dst[i + t * 128] = __float2half_rn(src[i + t * 128]);
}

__global__ void __launch_bounds__(256) biasfill_k(
    const float* __restrict__ bq, float* __restrict__ bias2)
{
    int l = blockIdx.x;
    for (int t = threadIdx.x; t < 1024; t += 256)
        bias2[l * 1024 + t] = (t < 512) ? 0.f : bq[l * 512 + t - 512];
}

// ---------------- fused attention v2: prefetch + half2 ----------------
__global__ void __launch_bounds__(256) attn_k(
    const float* __restrict__ qh, const __half* __restrict__ KhatH,
    const int* __restrict__ nbr_r, const int* __restrict__ nbr_e,
    const int* __restrict__ remap,
    const float* __restrict__ masks,
    const float* __restrict__ hW0, const __half* __restrict__ eW2,
    const __half* __restrict__ rW1H,
    __half* __restrict__ ctxH)
{
    const int b = blockIdx.x;
    const int tid = threadIdx.x;
    const int lane = tid & 31, w = tid >> 5;

    __shared__ float s_q[512];
    __shared__ float s_attn[HH * 64];
    __shared__ int   s_nbr[NN], s_nbe[NN], s_act[NN];
    __shared__ int   s_wc[2];
    __shared__ unsigned s_kb[2];
    __shared__ __align__(16) __half s_val[3][1024];   // [stage]: eW2 row | rW1 row

    s_q[tid]       = qh[(size_t)b * 512 + tid];
    s_q[tid + 256] = qh[(size_t)b * 512 + tid + 256];
    s_attn[tid] = -1e31f; s_attn[tid + 256] = -1e31f;
    if (tid < NN) {
        s_nbr[tid] = nbr_r[b * NN + tid];
        s_nbe[tid] = remap[nbr_e[b * NN + tid]];
    }
    if (w < 2) {
        bool keep = masks[b * NN + tid] > 0.5f;
        unsigned bal = __ballot_sync(0xffffffffu, keep);
        if (lane == 0) { s_wc[w] = __popc(bal); s_kb[w] = bal; }
    }
    __syncthreads();
    if (w < 2) {
        unsigned bal = s_kb[w];
        if ((bal >> lane) & 1u) {
            int rank = __popc(bal & ((1u << lane) - 1u)) + (w ? s_wc[0] : 0);
            s_act[rank] = tid;
        }
    }
    const int nact = s_wc[0] + s_wc[1];
    __syncthreads();

    // scores over active neighbors only (Khat fp16, half2 loads)
    {
        float q0 = s_q[w * 64 + 2 * lane], q1 = s_q[w * 64 + 2 * lane + 1];
        for (int idx = 0; idx < nact; idx++) {
            int n = s_act[idx];
            const __half* kr = KhatH + (size_t)s_nbr[n] * 512 + w * 64;
            float2 kf = __half22float2(*(const __half2*)&kr[2 * lane]);
            float p = q0 * kf.x + q1 * kf.y;
#pragma unroll
            for (int o = 16; o; o >>= 1) p += __shfl_xor_sync(0xffffffffu, p, o);
            if (lane == 0) s_attn[w * 64 + n] = p * 0.125f;
        }
    }
    __syncwarp();
    {
        float s0 = s_attn[w * 64 + lane], s1 = s_attn[w * 64 + lane + 32];
        float m = fmaxf(s0, s1);
#pragma unroll
        for (int o = 16; o; o >>= 1) m = fmaxf(m, __shfl_xor_sync(0xffffffffu, m, o));
        float e0 = expf(s0 - m), e1 = expf(s1 - m);
        float sum = e0 + e1;
#pragma unroll
        for (int o = 16; o; o >>= 1) sum += __shfl_xor_sync(0xffffffffu, sum, o);
        float inv = 1.f / sum;
        s_attn[w * 64 + lane]      = e0 * inv;
        s_attn[w * 64 + lane + 32] = e1 * inv;
    }
    __syncthreads();

    // value pass: 3-stage cp.async prefetch of (eW2 | rW1) rows
    auto prefetch = [&](int ii) {
        if (ii < nact && tid < 128) {
            int n = s_act[ii];
            int s = ii % 3;
            if (tid < 64)
                cp16(s2u(&s_val[s][tid * 8]), eW2 + (size_t)s_nbe[n] * 512 + tid * 8);
            else
                cp16(s2u(&s_val[s][512 + (tid - 64) * 8]),
                     rW1H + (size_t)s_nbr[n] * 512 + (tid - 64) * 8);
        }
        cp_commit();
    };
    prefetch(0); prefetch(1); prefetch(2);

    const float2 hw0v = *(const float2*)&hW0[(size_t)b * 512 + 2 * tid];
    float acc[HH][2];
#pragma unroll
    for (int hh = 0; hh < HH; hh++) { acc[hh][0] = 0.f; acc[hh][1] = 0.f; }

    for (int ii = 0; ii < nact; ii++) {
        cp_wait<2>();
        __syncthreads();
        int s = ii % 3, n = s_act[ii];
        float2 ev = __half22float2(*(const __half2*)&s_val[s][2 * tid]);
        float2 rv = __half22float2(*(const __half2*)&s_val[s][512 + 2 * tid]);
        float v0 = hw0v.x + ev.x + rv.x;
        float v1 = hw0v.y + ev.y + rv.y;
        v0 = (v0 > 0.f) ? v0 : 0.01f * v0;
        v1 = (v1 > 0.f) ? v1 : 0.01f * v1;
#pragma unroll
        for (int hh = 0; hh < HH; hh++) {
            float a = s_attn[hh * 64 + n];
            acc[hh][0] += a * v0;
            acc[hh][1] += a * v1;
        }
        __syncthreads();
        prefetch(ii + 3);
    }
#pragma unroll
    for (int hh = 0; hh < HH; hh++) {
        *(__half2*)&ctxH[((size_t)b * HH + hh) * 512 + 2 * tid] =
            __floats2half2_rn(acc[hh][0], acc[hh][1]);
    }
}

// ---------------- layernorm ----------------
__global__ void __launch_bounds__(128) ln_k(
    float* __restrict__ h, const float* __restrict__ x, const float* __restrict__ x2,
    const float* __restrict__ gamma, const float* __restrict__ beta,
    __half* __restrict__ hH)
{
    const int b = blockIdx.x, tid = threadIdx.x;
    __shared__ float sred[8];
    float4 hv = ((const float4*)(h + (size_t)b * 512))[tid];
    float4 xv = ((const float4*)(x + (size_t)b * 512))[tid];
    float v0 = hv.x + xv.x, v1 = hv.y + xv.y, v2 = hv.z + xv.z, v3 = hv.w + xv.w;
    if (x2) {
        float4 x2v = ((const float4*)(x2 + (size_t)b * 512))[tid];
        v0 += x2v.x; v1 += x2v.y; v2 += x2v.z; v3 += x2v.w;
    }

    float s = v0 + v1 + v2 + v3;
#pragma unroll
    for (int o = 16; o; o >>= 1) s += __shfl_xor_sync(0xffffffffu, s, o);
    if ((tid & 31) == 0) sred[tid >> 5] = s;
    __syncthreads();
    float mean = (sred[0] + sred[1] + sred[2] + sred[3]) * (1.f / 512.f);

    v0 -= mean; v1 -= mean; v2 -= mean; v3 -= mean;
    float sq = v0 * v0 + v1 * v1 + v2 * v2 + v3 * v3;
#pragma unroll
    for (int o = 16; o; o >>= 1) sq += __shfl_xor_sync(0xffffffffu, sq, o);
    if ((tid & 31) == 0) sred[4 + (tid >> 5)] = sq;
    __syncthreads();
    float var = (sred[4] + sred[5] + sred[6] + sred[7]) * (1.f / 512.f);
    float rstd = rsqrtf(var + 1e-5f);

    float4 g = ((const float4*)gamma)[tid];
    float4 be = ((const float4*)beta)[tid];
    float o0 = v0 * rstd * g.x + be.x;
    float o1 = v1 * rstd * g.y + be.y;
    float o2 = v2 * rstd * g.z + be.z;
    float o3 = v3 * rstd * g.w + be.w;
    float4 o; o.x = o0; o.y = o1; o.z = o2; o.w = o3;
    ((float4*)(h + (size_t)b * 512))[tid] = o;

    __half2* d = (__half2*)(hH + (size_t)b * 512 + tid * 4);
    d[0] = __floats2half2_rn(o0, o1);
    d[1] = __floats2half2_rn(o2, o3);
}

// ---------------- init ----------------
__global__ void __launch_bounds__(128) init_k(
    const int* __restrict__ e1, const int* __restrict__ qi,
    const float* __restrict__ emb_e, const float* __restrict__ emb_r,
    float* __restrict__ h, __half* __restrict__ actH,
    float* __restrict__ outq, int writeq)
{
    const int b = blockIdx.x, t = threadIdx.x;
    const float* se = emb_e + (size_t)e1[b] * 512;
    const float* sr = emb_r + (size_t)qi[b] * 512;
    for (int j = t; j < 512; j += 128) {
        float hv = se[j];
        h[(size_t)b * 512 + j] = hv;
        actH[(size_t)b * 512 + j] = __float2half_rn(hv);
        float q = sr[j];
        actH[(size_t)(BB + b) * 512 + j] = __float2half_rn(q);
        if (writeq) outq[(size_t)b * 512 + j] = q;
    }
}

__global__ void copy_k(float* __restrict__ out, const float* __restrict__ in)
{
    int i = blockIdx.x * 256 + threadIdx.x;
    out[i] = in[i];
}

// ---------------- launch ----------------
extern "C" void kernel_launch(void* const* d_in, const int* in_sizes, int n_in,
                              void* d_out, int out_size)
{
    const int*   e1    = (const int*)d_in[0];
    const int*   qidx  = (const int*)d_in[1];
    const int*   nbr_r = (const int*)d_in[2];
    const int*   nbr_e = (const int*)d_in[3];
    const float* masks = (const float*)d_in[4];
    const float* emb_e = (const float*)d_in[5];
    const float* emb_r = (const float*)d_in[6];
    const float* msg_W = (const float*)d_in[7];
    const float* msg_b = (const float*)d_in[8];
    const float* Wq    = (const float*)d_in[9];
    const float* bq    = (const float*)d_in[10];
    const float* Wk    = (const float*)d_in[11];
    const float* bk    = (const float*)d_in[12];
    const float* Wv    = (const float*)d_in[13];
    const float* bv    = (const float*)d_in[14];
    const float* ffW1  = (const float*)d_in[15];
    const float* ffb1  = (const float*)d_in[16];
    const float* ffW2  = (const float*)d_in[17];
    const float* ffb2  = (const float*)d_in[18];
    const float* ln1g  = (const float*)d_in[19];
    const float* ln1b  = (const float*)d_in[20];
    const float* ln2g  = (const float*)d_in[21];
    const float* ln2b  = (const float*)d_in[22];
    float* out = (float*)d_out;

    __half *p_embeH, *p_eW2H, *p_embrH, *p_actH, *p_ctxH, *p_ffH, *p_rW1H, *p_KhatH;
    __half *p_W2h, *p_W1h, *p_Wcomb, *p_Wkh, *p_Wvh, *p_F1h, *p_F2h;
    float *p_bias2, *p_h, *p_hw0qh, *p_x;
    unsigned char* p_flag; int *p_cnt, *p_list, *p_remap;
    cudaGetSymbolAddress((void**)&p_embeH, g_embeH);
    cudaGetSymbolAddress((void**)&p_eW2H,  g_eW2H);
    cudaGetSymbolAddress((void**)&p_embrH, g_embrH);
    cudaGetSymbolAddress((void**)&p_actH,  g_actH);
    cudaGetSymbolAddress((void**)&p_ctxH,  g_ctxH);
    cudaGetSymbolAddress((void**)&p_ffH,   g_ffH);
    cudaGetSymbolAddress((void**)&p_rW1H,  g_rW1H);
    cudaGetSymbolAddress((void**)&p_KhatH, g_KhatH);
    cudaGetSymbolAddress((void**)&p_W2h,   g_W2h);
    cudaGetSymbolAddress((void**)&p_W1h,   g_W1h);
    cudaGetSymbolAddress((void**)&p_Wcomb, g_Wcomb);
    cudaGetSymbolAddress((void**)&p_Wkh,   g_Wkh);
    cudaGetSymbolAddress((void**)&p_Wvh,   g_Wvh);
    cudaGetSymbolAddress((void**)&p_F1h,   g_F1h);
    cudaGetSymbolAddress((void**)&p_F2h,   g_F2h);
    cudaGetSymbolAddress((void**)&p_bias2, g_bias2);
    cudaGetSymbolAddress((void**)&p_h,     g_h);
    cudaGetSymbolAddress((void**)&p_hw0qh, g_hw0qh);
    cudaGetSymbolAddress((void**)&p_x,     g_x);
    cudaGetSymbolAddress((void**)&p_flag,  g_flag);
    cudaGetSymbolAddress((void**)&p_cnt,   g_cnt);
    cudaGetSymbolAddress((void**)&p_list,  g_list);
    cudaGetSymbolAddress((void**)&p_remap, g_remap);

    const int SMK_128 = 512 + 3 * ((128 + 128) * 128);  // 98816
    const int SMK_64  = 512 + 3 * ((128 + 64) * 128);   // 74240
    cudaFuncSetAttribute((gemm_f2<128, 0>), cudaFuncAttributeMaxDynamicSharedMemorySize, SMK_128);
    cudaFuncSetAttribute((gemm_f2<128, 1>), cudaFuncAttributeMaxDynamicSharedMemorySize, SMK_128);
    cudaFuncSetAttribute((gemm_f2<64, 0>),  cudaFuncAttributeMaxDynamicSharedMemorySize, SMK_64);

    int writeq = (out_size >= 2 * BB * DD) ? 1 : 0;

    // used-row compaction (launches 1-4)
    zero_k<<<(EE + 255) / 256, 256>>>(p_flag, p_cnt);
    mark_k<<<(BB * NN + 255) / 256, 256>>>(nbr_e, p_flag);
    compact_k<<<(EE + 255) / 256, 256>>>(p_flag, p_cnt, p_list, p_remap);
    convGather_k<<<EE, 128>>>(emb_e, p_list, p_cnt, p_embeH);
    // launch 5: W2 conversion
    convT_k<<<dim3(8, 8, 1), 256>>>(msg_W + 1024 * 512, 512, 64, 0, 512, p_W2h, 0);
    // launch 6 (profiled): eW2 = used_rows(emb_e) @ W2 + msg_b (compact M)
    gemm_f2<128, 1><<<dim3(4, (EE + 127) / 128), 256, SMK_128>>>(
        p_embeH, 512, 0, nullptr, EE, p_W2h, 0, 512,
        msg_b, 0, p_eW2H, 512, 0, 0, 0, 0, 0, p_cnt);

    init_k<<<BB, 128>>>(e1, qidx, emb_e, emb_r, p_h, p_actH, out + (size_t)BB * DD, writeq);
    convT_k<<<dim3(8, 8, 1), 256>>>(msg_W + 512 * 512, 512, 64, 0, 512, p_W1h, 0);
    convA_h<<<RR, 128>>>(emb_r, p_embrH);
    biasfill_k<<<LL, 256>>>(bq, p_bias2);
    convT_k<<<dim3(8, 8, LL), 256>>>(msg_W, 512, 64, 0, 512, p_Wcomb, 524288);
    convT_k<<<dim3(8, 8, LL), 256>>>(Wq, 64, 32768, 262144, 512, p_Wcomb + 262144, 524288);
    convT_k<<<dim3(8, 8, LL), 256>>>(Wk, 64, 32768, 262144, 512, p_Wkh, 262144);
    convT_k<<<dim3(8, 8, LL), 256>>>(Wv, 64, 32768, 262144, 512, p_Wvh, 262144);
    convT_k<<<dim3(8, 32, LL), 256>>>(ffW1, 2048, 64, 1048576, 512, p_F1h, 1048576);
    convT_k<<<dim3(32, 8, LL), 256>>>(ffW2, 512, 64, 1048576, 2048, p_F2h, 1048576);

    // rW1H = half(emb_r @ W1)
    gemm_f2<128, 1><<<dim3(4, 4), 256, SMK_128>>>(
        p_embrH, 512, 0, nullptr, RR, p_W1h, 0, 512,
        nullptr, 0, p_rW1H, 512, 0, 0, 0, 0, 0, nullptr);
    // KhatH[l] = half(emb_r @ Wk[l] + bk[l])
    gemm_f2<128, 1><<<dim3(4, 4, LL), 256, SMK_128>>>(
        p_embrH, 512, 0, nullptr, RR, p_Wkh, 262144, 512,
        bk, 512, p_KhatH, 512, 0, (long long)RR * 512, 0, 0, 0, nullptr);

    for (int l = 0; l < LL; l++) {
        // z=0: hW0 = h @ W0; z=1: qh = embq @ Wq[l] + bq[l]
        gemm_f2<128, 0><<<dim3(4, 16, 2), 256, SMK_128>>>(
            p_actH, 512, (long long)BB * 512, nullptr, BB,
            p_Wcomb + (size_t)l * 2 * 262144, 262144, 512,
            p_bias2 + l * 1024, 512,
            p_hw0qh, 512, 0, (long long)BB * 512, 0, 0, 0, nullptr);
        attn_k<<<BB, 256>>>(p_hw0qh + (size_t)BB * 512, p_KhatH + (size_t)l * RR * 512,
                            nbr_r, nbr_e, p_remap, masks, p_hw0qh, p_eW2H, p_rW1H, p_ctxH);
        // x = ctx @ Wv[l] + bv[l] (z = head)
        gemm_f2<64, 0><<<dim3(1, 16, 8), 256, SMK_64>>>(
            p_ctxH, 4096, 512, nullptr, BB,
            p_Wvh + (size_t)l * 262144, 32768, 512,
            bv + l * 512, 0, p_x, 512, 64, 0, 0, 0, 0, nullptr);
        ln_k<<<BB, 128>>>(p_h, p_x, nullptr, ln1g + l * 512, ln1b + l * 512, p_actH);
        // ffH = fp16(relu(h @ F1 + b1))
        gemm_f2<128, 1><<<dim3(16, 16), 256, SMK_128>>>(
            p_actH, 512, 0, nullptr, BB,
            p_F1h + (size_t)l * 1048576, 0, 512,
            ffb1 + l * 2048, 0, p_ffH, 2048, 0, 0, 0, 0, 1, nullptr);
        // x0/x1 = split-K halves of ff @ F2 (+ b2 on z=0)
        gemm_f2<128, 0><<<dim3(4, 16, 2), 256, SMK_128>>>(
            p_ffH, 2048, 0, nullptr, BB,
            p_F2h + (size_t)l * 1048576, 0, 2048,
            ffb2 + l * 512, 0, p_x, 512, 0, (long long)BB * 512, 1, 16, 0, nullptr);
        ln_k<<<BB, 128>>>(p_h, p_x, p_x + (size_t)BB * 512, ln2g + l * 512, ln2b + l * 512, p_actH);
    }

    copy_k<<<(BB * DD) / 256, 256>>>(out, p_h);
}

// round 16
// speedup vs baseline: 1.2057x; 1.0521x over previous
#include <cuda_runtime.h>
#include <cuda_fp16.h>
#include <cstdint>

#define BB 2048
#define NN 64
#define DD 512
#define HH 8
#define LL 3
#define FFD 2048
#define RR 400
#define EE 100000

// ---------------- device scratch ----------------
__device__ __align__(256) __half g_embeH[EE * 512];        // used-rows (compact) fp16 emb_e
__device__ __align__(256) __half g_eW2H[EE * 512];         // compact eW2 rows
__device__ __align__(256) __half g_embrH[RR * 512];
__device__ __align__(256) __half g_actH[2 * BB * 512];     // [0]=hH, [1]=embqH
__device__ __align__(256) __half g_ctxH[BB * HH * 512];
__device__ __align__(256) __half g_ffH[BB * 2048];
__device__ __align__(256) __half g_rW1H[RR * 512];
__device__ __align__(256) __half g_KhatH[LL * RR * 512];
__device__ __align__(256) __half g_W2h[512 * 512];
__device__ __align__(256) __half g_W1h[512 * 512];
__device__ __align__(256) __half g_Wcomb[LL * 2 * 512 * 512];  // [l][0]=W0, [l][1]=Wq[l]
__device__ __align__(256) __half g_Wkh[LL * 512 * 512];
__device__ __align__(256) __half g_Wvh[LL * 512 * 512];
__device__ __align__(256) __half g_F1h[LL * 2048 * 512];
__device__ __align__(256) __half g_F2h[LL * 512 * 2048];
__device__ __align__(256) float  g_bias2[LL * 1024];           // [l]: 512 zeros | bq[l]
__device__ __align__(256) float  g_h[BB * 512];
__device__ __align__(256) float  g_hw0qh[2 * BB * 512];        // [0]=hW0, [1]=qh
__device__ __align__(256) float  g_x[2 * BB * 512];
__device__ unsigned char g_flag[EE];
__device__ int g_cnt;
__device__ int g_list[EE];
__device__ int g_remap[EE];

// ---------------- helpers ----------------
__device__ __forceinline__ uint32_t s2u(const void* p) {
    uint32_t a;
    asm("{ .reg .u64 t; cvta.to.shared.u64 t, %1; cvt.u32.u64 %0, t; }" : "=r"(a) : "l"(p));
    return a;
}
__device__ __forceinline__ void cp16(uint32_t d, const void* s) {
    asm volatile("cp.async.cg.shared.global [%0], [%1], 16;" :: "r"(d), "l"(s));
}
__device__ __forceinline__ void cp_commit() { asm volatile("cp.async.commit_group;" ::: "memory"); }
template<int G> __device__ __forceinline__ void cp_wait() {
    asm volatile("cp.async.wait_group %0;" :: "n"(G) : "memory");
}
__device__ __forceinline__ void ldm4(uint32_t& r0, uint32_t& r1, uint32_t& r2, uint32_t& r3, uint32_t a) {
    asm volatile("ldmatrix.sync.aligned.m8n8.x4.shared.b16 {%0,%1,%2,%3}, [%4];"
        : "=r"(r0), "=r"(r1), "=r"(r2), "=r"(r3) : "r"(a));
}
__device__ __forceinline__ void mma_f16(float* c, const uint32_t* a, const uint32_t* b) {
    asm volatile(
        "mma.sync.aligned.m16n8k16.row.col.f32.f16.f16.f32 "
        "{%0,%1,%2,%3}, {%4,%5,%6,%7}, {%8,%9}, {%0,%1,%2,%3};"
        : "+f"(c[0]), "+f"(c[1]), "+f"(c[2]), "+f"(c[3])
        : "r"(a[0]), "r"(a[1]), "r"(a[2]), "r"(a[3]), "r"(b[0]), "r"(b[1]));
}
// SW128: 16B chunk swizzle within 128B rows
__device__ __forceinline__ uint32_t ofs128(int row, int c) {
    return (uint32_t)(row * 128 + ((c ^ (row & 7)) << 4));
}

// ---------------- fp16 HMMA GEMM, BK=64, 3-stage cp.async pipeline ----------------
template<int BN, int OUTH>
__global__ void __launch_bounds__(256, 2) gemm_f2(
    const __half* __restrict__ A, int a_ld, long long za,
    const int* __restrict__ gidx, int M,
    const __half* __restrict__ B, long long zb, int K,
    const float* __restrict__ bias, long long zbias,
    void* __restrict__ Cv, int ldc, int zn, long long zc,
    int kz, int kspan, int act, const int* __restrict__ Mdyn)
{
    constexpr int WARPS_N = BN / 32;
    constexpr int WARPS_M = 8 / WARPS_N;
    constexpr int WM = 128 / WARPS_M;
    constexpr int MAT_M = WM / 16;
    constexpr int STAGE = (128 + BN) * 128;
    constexpr int UNITS = (128 + BN) * 8;

    extern __shared__ __align__(1024) char smem[];
    int* s_idx = (int*)smem;
    const uint32_t sb = s2u(smem);
    const int tid = threadIdx.x, w = tid >> 5, lane = tid & 31;
    const int wm = w / WARPS_N, wn = w % WARPS_N;
    const int gm0 = blockIdx.y * 128;
    const int bn0 = blockIdx.x * BN;
    const int z = blockIdx.z;
    const int n0g = bn0 + z * zn;

    if (Mdyn) M = *Mdyn;
    if (gm0 >= M) return;

    A += (size_t)z * za;
    B += (size_t)z * zb;
    if (kz && z > 0) bias = nullptr;
    else if (bias) bias += (size_t)z * zbias;

    if (tid < 128) {
        int gr = gm0 + tid;
        if (gr >= M) gr = M - 1;
        s_idx[tid] = gidx ? gidx[gr] : gr;
    }
    __syncthreads();

    const int NCH = K >> 6;
    const int kbeg = kz ? z * kspan : 0;
    const int kcnt = kz ? kspan : NCH;

    auto load_chunk = [&](int c) {
        int s = c % 3;
        int koff = c * 64;
        uint32_t st = sb + 512 + s * STAGE;
#pragma unroll
        for (int it = 0; it < UNITS / 256; it++) {
            int u = tid + it * 256;
            if (u < 1024) {
                int r = u >> 3, c16 = u & 7;
                cp16(st + ofs128(r, c16),
                     A + (size_t)s_idx[r] * a_ld + koff + c16 * 8);
            } else {
                int v = u - 1024;
                int n = v >> 3, c16 = v & 7;
                cp16(st + 16384 + ofs128(n, c16),
                     B + (size_t)(bn0 + n) * K + koff + c16 * 8);
            }
        }
        cp_commit();
    };

    float acc[MAT_M][4][4];
#pragma unroll
    for (int i = 0; i < MAT_M; i++)
#pragma unroll
        for (int j = 0; j < 4; j++)
#pragma unroll
            for (int q = 0; q < 4; q++) acc[i][j][q] = 0.f;

    load_chunk(kbeg);
    load_chunk(kbeg + 1);

    const int r8 = lane & 7, sel = lane >> 3;

    for (int cc = 0; cc < kcnt; cc++) {
        int c = kbeg + cc;
        cp_wait<1>();
        __syncthreads();
        uint32_t stA = sb + 512 + (c % 3) * STAGE;
        uint32_t stB = stA + 16384;
#pragma unroll
        for (int kt = 0; kt < 4; kt++) {
            uint32_t a[MAT_M][4];
#pragma unroll
            for (int i = 0; i < MAT_M; i++) {
                int ar = wm * WM + i * 16 + r8 + (sel & 1) * 8;
                int ac = kt * 2 + (sel >> 1);
                ldm4(a[i][0], a[i][1], a[i][2], a[i][3], stA + ofs128(ar, ac));
            }
            uint32_t b[4][2];
#pragma unroll
            for (int p = 0; p < 2; p++) {
                int br = wn * 32 + p * 16 + r8 + (sel >> 1) * 8;
                int bc = kt * 2 + (sel & 1);
                uint32_t t0, t1, t2, t3;
                ldm4(t0, t1, t2, t3, stB + ofs128(br, bc));
                b[2 * p][0] = t0; b[2 * p][1] = t1;
                b[2 * p + 1][0] = t2; b[2 * p + 1][1] = t3;
            }
#pragma unroll
            for (int i = 0; i < MAT_M; i++)
#pragma unroll
                for (int j = 0; j < 4; j++)
                    mma_f16(acc[i][j], a[i], b[j]);
        }
        if (cc + 2 < kcnt) load_chunk(c + 2);
        else cp_commit();
    }

    const int g = lane >> 2, tig = lane & 3;
#pragma unroll
    for (int i = 0; i < MAT_M; i++) {
#pragma unroll
        for (int half = 0; half < 2; half++) {
            int m = gm0 + wm * WM + i * 16 + g + half * 8;
            if (m < M) {
#pragma unroll
                for (int j = 0; j < 4; j++) {
                    int nc = n0g + wn * 32 + j * 8 + tig * 2;
                    float v0 = acc[i][j][half * 2 + 0];
                    float v1 = acc[i][j][half * 2 + 1];
                    if (bias) { v0 += bias[nc]; v1 += bias[nc + 1]; }
                    if (act)  { v0 = fmaxf(v0, 0.f); v1 = fmaxf(v1, 0.f); }
                    if (OUTH) {
                        __half* Ch = (__half*)Cv + (size_t)z * zc;
                        *(__half2*)&Ch[(size_t)m * ldc + nc] = __floats2half2_rn(v0, v1);
                    } else {
                        float* Cf = (float*)Cv + (size_t)z * zc;
                        float2 o; o.x = v0; o.y = v1;
                        *(float2*)&Cf[(size_t)m * ldc + nc] = o;
                    }
                }
            }
        }
    }
}

// ---------------- compaction of used entity rows ----------------
__global__ void __launch_bounds__(256) zero_k(unsigned char* flag, int* cnt)
{
    int i = blockIdx.x * 256 + threadIdx.x;
    if (i < EE) flag[i] = 0;
    if (i == 0) *cnt = 0;
}
__global__ void __launch_bounds__(256) mark_k(const int* __restrict__ nbe, unsigned char* flag)
{
    int i = blockIdx.x * 256 + threadIdx.x;
    if (i < BB * NN) flag[nbe[i]] = 1;
}
__global__ void __launch_bounds__(256) compact_k(
    const unsigned char* __restrict__ flag, int* cnt, int* list, int* remap)
{
    int e = blockIdx.x * 256 + threadIdx.x;
    if (e < EE && flag[e]) {
        int p = atomicAdd(cnt, 1);
        list[p] = e;
        remap[e] = p;
    }
}
// one block per compact row: fully coalesced float4 gather + half2 store
__global__ void __launch_bounds__(128) convGather_k(
    const float* __restrict__ emb_e, const int* __restrict__ list,
    const int* __restrict__ cnt, __half* __restrict__ dst)
{
    int row = blockIdx.x;
    if (row >= *cnt) return;
    const float4* s = (const float4*)(emb_e + (size_t)list[row] * 512);
    float4 v = s[threadIdx.x];
    __half2 a = __floats2half2_rn(v.x, v.y);
    __half2 b = __floats2half2_rn(v.z, v.w);
    uint2 o;
    o.x = *(uint32_t*)&a;
    o.y = *(uint32_t*)&b;
    *(uint2*)(dst + (size_t)row * 512 + threadIdx.x * 4) = o;
}

// ---------------- coalesced transpose weight conversion ----------------
__global__ void __launch_bounds__(256) convT_k(
    const float* __restrict__ W, int str_k, int str_h, long long wmat,
    int K, __half* __restrict__ B2, long long bmat)
{
    __shared__ float t[64][66];
    W += (size_t)blockIdx.z * wmat;
    B2 += (size_t)blockIdx.z * bmat;
    const int k0 = blockIdx.x * 64, n0 = blockIdx.y * 64;
    const float* Wp = W + (size_t)(n0 >> 6) * str_h;
    const int c = threadIdx.x & 63;
    const int r0 = threadIdx.x >> 6;
#pragma unroll
    for (int i = 0; i < 16; i++) {
        int r = r0 + i * 4;
        t[c][r] = Wp[(size_t)(k0 + r) * str_k + c];
    }
    __syncthreads();
    const int ck = threadIdx.x & 31;
    const int rn0 = threadIdx.x >> 5;
#pragma unroll
    for (int i = 0; i < 8; i++) {
        int rn = rn0 + i * 8;
        float2 f = *(const float2*)&t[rn][ck * 2];
        *(__half2*)&B2[(size_t)(n0 + rn) * K + k0 + ck * 2] = __floats2half2_rn(f.x, f.y);
    }
}

__global__ void __launch_bounds__(128) convA_h(
    const float* __restrict__ src, __half* __restrict__ dst)
{
    size_t i = (size_t)blockIdx.x * 512 + threadIdx.x;
#pragma unroll
    for (int t = 0; t < 4; t++)
        dst[i + t * 128] = __float2half_rn(src[i + t * 128]);
}

__global__ void __launch_bounds__(256) biasfill_k(
    const float* __restrict__ bq, float* __restrict__ bias2)
{
    int l = blockIdx.x;
    for (int t = threadIdx.x; t < 1024; t += 256)
        bias2[l * 1024 + t] = (t < 512) ? 0.f : bq[l * 512 + t - 512];
}

// ---------------- fused attention v3: 4-stage prefetch, single sync per iter ----------------
__global__ void __launch_bounds__(256) attn_k(
    const float* __restrict__ qh, const __half* __restrict__ KhatH,
    const int* __restrict__ nbr_r, const int* __restrict__ nbr_e,
    const int* __restrict__ remap,
    const float* __restrict__ masks,
    const float* __restrict__ hW0, const __half* __restrict__ eW2,
    const __half* __restrict__ rW1H,
    __half* __restrict__ ctxH)
{
    const int b = blockIdx.x;
    const int tid = threadIdx.x;
    const int lane = tid & 31, w = tid >> 5;

    __shared__ float s_q[512];
    __shared__ float s_attn[HH * 64];
    __shared__ int   s_nbr[NN], s_nbe[NN], s_act[NN];
    __shared__ int   s_wc[2];
    __shared__ unsigned s_kb[2];
    __shared__ __align__(16) __half s_val[4][1024];   // [stage]: eW2 row | rW1 row

    s_q[tid]       = qh[(size_t)b * 512 + tid];
    s_q[tid + 256] = qh[(size_t)b * 512 + tid + 256];
    s_attn[tid] = -1e31f; s_attn[tid + 256] = -1e31f;
    if (tid < NN) {
        s_nbr[tid] = nbr_r[b * NN + tid];
        s_nbe[tid] = remap[nbr_e[b * NN + tid]];
    }
    if (w < 2) {
        bool keep = masks[b * NN + tid] > 0.5f;
        unsigned bal = __ballot_sync(0xffffffffu, keep);
        if (lane == 0) { s_wc[w] = __popc(bal); s_kb[w] = bal; }
    }
    __syncthreads();
    if (w < 2) {
        unsigned bal = s_kb[w];
        if ((bal >> lane) & 1u) {
            int rank = __popc(bal & ((1u << lane) - 1u)) + (w ? s_wc[0] : 0);
            s_act[rank] = tid;
        }
    }
    const int nact = s_wc[0] + s_wc[1];
    __syncthreads();

    // scores over active neighbors only (Khat fp16, half2 loads)
    {
        float q0 = s_q[w * 64 + 2 * lane], q1 = s_q[w * 64 + 2 * lane + 1];
#pragma unroll 2
        for (int idx = 0; idx < nact; idx++) {
            int n = s_act[idx];
            const __half* kr = KhatH + (size_t)s_nbr[n] * 512 + w * 64;
            float2 kf = __half22float2(*(const __half2*)&kr[2 * lane]);
            float p = q0 * kf.x + q1 * kf.y;
#pragma unroll
            for (int o = 16; o; o >>= 1) p += __shfl_xor_sync(0xffffffffu, p, o);
            if (lane == 0) s_attn[w * 64 + n] = p * 0.125f;
        }
    }
    __syncwarp();
    {
        float s0 = s_attn[w * 64 + lane], s1 = s_attn[w * 64 + lane + 32];
        float m = fmaxf(s0, s1);
#pragma unroll
        for (int o = 16; o; o >>= 1) m = fmaxf(m, __shfl_xor_sync(0xffffffffu, m, o));
        float e0 = expf(s0 - m), e1 = expf(s1 - m);
        float sum = e0 + e1;
#pragma unroll
        for (int o = 16; o; o >>= 1) sum += __shfl_xor_sync(0xffffffffu, sum, o);
        float inv = 1.f / sum;
        s_attn[w * 64 + lane]      = e0 * inv;
        s_attn[w * 64 + lane + 32] = e1 * inv;
    }
    __syncthreads();

    // value pass: 4-stage cp.async prefetch (distance 3) -> single barrier per iteration.
    // prefetch(ii+3) writes stage (ii+3)&3 == (ii-1)&3, whose reads finished at
    // iteration ii-1 and are fenced by the barrier at the top of iteration ii.
    auto prefetch = [&](int ii) {
        if (ii < nact && tid < 128) {
            int n = s_act[ii];
            int s = ii & 3;
            if (tid < 64)
                cp16(s2u(&s_val[s][tid * 8]), eW2 + (size_t)s_nbe[n] * 512 + tid * 8);
            else
                cp16(s2u(&s_val[s][512 + (tid - 64) * 8]),
                     rW1H + (size_t)s_nbr[n] * 512 + (tid - 64) * 8);
        }
        cp_commit();
    };
    prefetch(0); prefetch(1); prefetch(2);

    const float2 hw0v = *(const float2*)&hW0[(size_t)b * 512 + 2 * tid];
    float acc[HH][2];
#pragma unroll
    for (int hh = 0; hh < HH; hh++) { acc[hh][0] = 0.f; acc[hh][1] = 0.f; }

    for (int ii = 0; ii < nact; ii++) {
        cp_wait<2>();
        __syncthreads();
        int s = ii & 3, n = s_act[ii];
        float2 ev = __half22float2(*(const __half2*)&s_val[s][2 * tid]);
        float2 rv = __half22float2(*(const __half2*)&s_val[s][512 + 2 * tid]);
        float v0 = hw0v.x + ev.x + rv.x;
        float v1 = hw0v.y + ev.y + rv.y;
        v0 = (v0 > 0.f) ? v0 : 0.01f * v0;
        v1 = (v1 > 0.f) ? v1 : 0.01f * v1;
#pragma unroll
        for (int hh = 0; hh < HH; hh++) {
            float a = s_attn[hh * 64 + n];
            acc[hh][0] += a * v0;
            acc[hh][1] += a * v1;
        }
        prefetch(ii + 3);
    }
#pragma unroll
    for (int hh = 0; hh < HH; hh++) {
        *(__half2*)&ctxH[((size_t)b * HH + hh) * 512 + 2 * tid] =
            __floats2half2_rn(acc[hh][0], acc[hh][1]);
    }
}

// ---------------- layernorm (split in/out) ----------------
__global__ void __launch_bounds__(128) ln_k(
    const float* __restrict__ hin, float* __restrict__ hout,
    const float* __restrict__ x, const float* __restrict__ x2,
    const float* __restrict__ gamma, const float* __restrict__ beta,
    __half* __restrict__ hH)
{
    const int b = blockIdx.x, tid = threadIdx.x;
    __shared__ float sred[8];
    float4 hv = ((const float4*)(hin + (size_t)b * 512))[tid];
    float4 xv = ((const float4*)(x + (size_t)b * 512))[tid];
    float v0 = hv.x + xv.x, v1 = hv.y + xv.y, v2 = hv.z + xv.z, v3 = hv.w + xv.w;
    if (x2) {
        float4 x2v = ((const float4*)(x2 + (size_t)b * 512))[tid];
        v0 += x2v.x; v1 += x2v.y; v2 += x2v.z; v3 += x2v.w;
    }

    float s = v0 + v1 + v2 + v3;
#pragma unroll
    for (int o = 16; o; o >>= 1) s += __shfl_xor_sync(0xffffffffu, s, o);
    if ((tid & 31) == 0) sred[tid >> 5] = s;
    __syncthreads();
    float mean = (sred[0] + sred[1] + sred[2] + sred[3]) * (1.f / 512.f);

    v0 -= mean; v1 -= mean; v2 -= mean; v3 -= mean;
    float sq = v0 * v0 + v1 * v1 + v2 * v2 + v3 * v3;
#pragma unroll
    for (int o = 16; o; o >>= 1) sq += __shfl_xor_sync(0xffffffffu, sq, o);
    if ((tid & 31) == 0) sred[4 + (tid >> 5)] = sq;
    __syncthreads();
    float var = (sred[4] + sred[5] + sred[6] + sred[7]) * (1.f / 512.f);
    float rstd = rsqrtf(var + 1e-5f);

    float4 g = ((const float4*)gamma)[tid];
    float4 be = ((const float4*)beta)[tid];
    float o0 = v0 * rstd * g.x + be.x;
    float o1 = v1 * rstd * g.y + be.y;
    float o2 = v2 * rstd * g.z + be.z;
    float o3 = v3 * rstd * g.w + be.w;
    float4 o; o.x = o0; o.y = o1; o.z = o2; o.w = o3;
    ((float4*)(hout + (size_t)b * 512))[tid] = o;

    __half2* d = (__half2*)(hH + (size_t)b * 512 + tid * 4);
    d[0] = __floats2half2_rn(o0, o1);
    d[1] = __floats2half2_rn(o2, o3);
}

// ---------------- init ----------------
__global__ void __launch_bounds__(128) init_k(
    const int* __restrict__ e1, const int* __restrict__ qi,
    const float* __restrict__ emb_e, const float* __restrict__ emb_r,
    float* __restrict__ h, __half* __restrict__ actH,
    float* __restrict__ outq, int writeq)
{
    const int b = blockIdx.x, t = threadIdx.x;
    const float* se = emb_e + (size_t)e1[b] * 512;
    const float* sr = emb_r + (size_t)qi[b] * 512;
    for (int j = t; j < 512; j += 128) {
        float hv = se[j];
        h[(size_t)b * 512 + j] = hv;
        actH[(size_t)b * 512 + j] = __float2half_rn(hv);
        float q = sr[j];
        actH[(size_t)(BB + b) * 512 + j] = __float2half_rn(q);
        if (writeq) outq[(size_t)b * 512 + j] = q;
    }
}

// ---------------- launch ----------------
extern "C" void kernel_launch(void* const* d_in, const int* in_sizes, int n_in,
                              void* d_out, int out_size)
{
    const int*   e1    = (const int*)d_in[0];
    const int*   qidx  = (const int*)d_in[1];
    const int*   nbr_r = (const int*)d_in[2];
    const int*   nbr_e = (const int*)d_in[3];
    const float* masks = (const float*)d_in[4];
    const float* emb_e = (const float*)d_in[5];
    const float* emb_r = (const float*)d_in[6];
    const float* msg_W = (const float*)d_in[7];
    const float* msg_b = (const float*)d_in[8];
    const float* Wq    = (const float*)d_in[9];
    const float* bq    = (const float*)d_in[10];
    const float* Wk    = (const float*)d_in[11];
    const float* bk    = (const float*)d_in[12];
    const float* Wv    = (const float*)d_in[13];
    const float* bv    = (const float*)d_in[14];
    const float* ffW1  = (const float*)d_in[15];
    const float* ffb1  = (const float*)d_in[16];
    const float* ffW2  = (const float*)d_in[17];
    const float* ffb2  = (const float*)d_in[18];
    const float* ln1g  = (const float*)d_in[19];
    const float* ln1b  = (const float*)d_in[20];
    const float* ln2g  = (const float*)d_in[21];
    const float* ln2b  = (const float*)d_in[22];
    float* out = (float*)d_out;

    __half *p_embeH, *p_eW2H, *p_embrH, *p_actH, *p_ctxH, *p_ffH, *p_rW1H, *p_KhatH;
    __half *p_W2h, *p_W1h, *p_Wcomb, *p_Wkh, *p_Wvh, *p_F1h, *p_F2h;
    float *p_bias2, *p_h, *p_hw0qh, *p_x;
    unsigned char* p_flag; int *p_cnt, *p_list, *p_remap;
    cudaGetSymbolAddress((void**)&p_embeH, g_embeH);
    cudaGetSymbolAddress((void**)&p_eW2H,  g_eW2H);
    cudaGetSymbolAddress((void**)&p_embrH, g_embrH);
    cudaGetSymbolAddress((void**)&p_actH,  g_actH);
    cudaGetSymbolAddress((void**)&p_ctxH,  g_ctxH);
    cudaGetSymbolAddress((void**)&p_ffH,   g_ffH);
    cudaGetSymbolAddress((void**)&p_rW1H,  g_rW1H);
    cudaGetSymbolAddress((void**)&p_KhatH, g_KhatH);
    cudaGetSymbolAddress((void**)&p_W2h,   g_W2h);
    cudaGetSymbolAddress((void**)&p_W1h,   g_W1h);
    cudaGetSymbolAddress((void**)&p_Wcomb, g_Wcomb);
    cudaGetSymbolAddress((void**)&p_Wkh,   g_Wkh);
    cudaGetSymbolAddress((void**)&p_Wvh,   g_Wvh);
    cudaGetSymbolAddress((void**)&p_F1h,   g_F1h);
    cudaGetSymbolAddress((void**)&p_F2h,   g_F2h);
    cudaGetSymbolAddress((void**)&p_bias2, g_bias2);
    cudaGetSymbolAddress((void**)&p_h,     g_h);
    cudaGetSymbolAddress((void**)&p_hw0qh, g_hw0qh);
    cudaGetSymbolAddress((void**)&p_x,     g_x);
    cudaGetSymbolAddress((void**)&p_flag,  g_flag);
    cudaGetSymbolAddress((void**)&p_cnt,   g_cnt);
    cudaGetSymbolAddress((void**)&p_list,  g_list);
    cudaGetSymbolAddress((void**)&p_remap, g_remap);

    const int SMK_128 = 512 + 3 * ((128 + 128) * 128);  // 98816
    const int SMK_64  = 512 + 3 * ((128 + 64) * 128);   // 74240
    cudaFuncSetAttribute((gemm_f2<128, 0>), cudaFuncAttributeMaxDynamicSharedMemorySize, SMK_128);
    cudaFuncSetAttribute((gemm_f2<128, 1>), cudaFuncAttributeMaxDynamicSharedMemorySize, SMK_128);
    cudaFuncSetAttribute((gemm_f2<64, 0>),  cudaFuncAttributeMaxDynamicSharedMemorySize, SMK_64);

    int writeq = (out_size >= 2 * BB * DD) ? 1 : 0;

    // used-row compaction (launches 1-4)
    zero_k<<<(EE + 255) / 256, 256>>>(p_flag, p_cnt);
    mark_k<<<(BB * NN + 255) / 256, 256>>>(nbr_e, p_flag);
    compact_k<<<(EE + 255) / 256, 256>>>(p_flag, p_cnt, p_list, p_remap);
    convGather_k<<<EE, 128>>>(emb_e, p_list, p_cnt, p_embeH);
    // launch 5: W2 conversion
    convT_k<<<dim3(8, 8, 1), 256>>>(msg_W + 1024 * 512, 512, 64, 0, 512, p_W2h, 0);
    // launch 6: eW2 = used_rows(emb_e) @ W2 + msg_b (compact M)
    gemm_f2<128, 1><<<dim3(4, (EE + 127) / 128), 256, SMK_128>>>(
        p_embeH, 512, 0, nullptr, EE, p_W2h, 0, 512,
        msg_b, 0, p_eW2H, 512, 0, 0, 0, 0, 0, p_cnt);

    init_k<<<BB, 128>>>(e1, qidx, emb_e, emb_r, p_h, p_actH, out + (size_t)BB * DD, writeq);
    convT_k<<<dim3(8, 8, 1), 256>>>(msg_W + 512 * 512, 512, 64, 0, 512, p_W1h, 0);
    convA_h<<<RR, 128>>>(emb_r, p_embrH);
    biasfill_k<<<LL, 256>>>(bq, p_bias2);
    convT_k<<<dim3(8, 8, LL), 256>>>(msg_W, 512, 64, 0, 512, p_Wcomb, 524288);
    convT_k<<<dim3(8, 8, LL), 256>>>(Wq, 64, 32768, 262144, 512, p_Wcomb + 262144, 524288);
    convT_k<<<dim3(8, 8, LL), 256>>>(Wk, 64, 32768, 262144, 512, p_Wkh, 262144);
    convT_k<<<dim3(8, 8, LL), 256>>>(Wv, 64, 32768, 262144, 512, p_Wvh, 262144);
    convT_k<<<dim3(8, 32, LL), 256>>>(ffW1, 2048, 64, 1048576, 512, p_F1h, 1048576);
    convT_k<<<dim3(32, 8, LL), 256>>>(ffW2, 512, 64, 1048576, 2048, p_F2h, 1048576);

    // rW1H = half(emb_r @ W1)
    gemm_f2<128, 1><<<dim3(4, 4), 256, SMK_128>>>(
        p_embrH, 512, 0, nullptr, RR, p_W1h, 0, 512,
        nullptr, 0, p_rW1H, 512, 0, 0, 0, 0, 0, nullptr);
    // KhatH[l] = half(emb_r @ Wk[l] + bk[l])
    gemm_f2<128, 1><<<dim3(4, 4, LL), 256, SMK_128>>>(
        p_embrH, 512, 0, nullptr, RR, p_Wkh, 262144, 512,
        bk, 512, p_KhatH, 512, 0, (long long)RR * 512, 0, 0, 0, nullptr);

    for (int l = 0; l < LL; l++) {
        // z=0: hW0 = h @ W0; z=1: qh = embq @ Wq[l] + bq[l]
        gemm_f2<128, 0><<<dim3(4, 16, 2), 256, SMK_128>>>(
            p_actH, 512, (long long)BB * 512, nullptr, BB,
            p_Wcomb + (size_t)l * 2 * 262144, 262144, 512,
            p_bias2 + l * 1024, 512,
            p_hw0qh, 512, 0, (long long)BB * 512, 0, 0, 0, nullptr);
        attn_k<<<BB, 256>>>(p_hw0qh + (size_t)BB * 512, p_KhatH + (size_t)l * RR * 512,
                            nbr_r, nbr_e, p_remap, masks, p_hw0qh, p_eW2H, p_rW1H, p_ctxH);
        // x = ctx @ Wv[l] + bv[l] (z = head)
        gemm_f2<64, 0><<<dim3(1, 16, 8), 256, SMK_64>>>(
            p_ctxH, 4096, 512, nullptr, BB,
            p_Wvh + (size_t)l * 262144, 32768, 512,
            bv + l * 512, 0, p_x, 512, 64, 0, 0, 0, 0, nullptr);
        ln_k<<<BB, 128>>>(p_h, p_h, p_x, nullptr, ln1g + l * 512, ln1b + l * 512, p_actH);
        // ffH = fp16(relu(h @ F1 + b1))
        gemm_f2<128, 1><<<dim3(16, 16), 256, SMK_128>>>(
            p_actH, 512, 0, nullptr, BB,
            p_F1h + (size_t)l * 1048576, 0, 512,
            ffb1 + l * 2048, 0, p_ffH, 2048, 0, 0, 0, 0, 1, nullptr);
        // x0/x1 = split-K halves of ff @ F2 (+ b2 on z=0)
        gemm_f2<128, 0><<<dim3(4, 16, 2), 256, SMK_128>>>(
            p_ffH, 2048, 0, nullptr, BB,
            p_F2h + (size_t)l * 1048576, 0, 2048,
            ffb2 + l * 512, 0, p_x, 512, 0, (long long)BB * 512, 1, 16, 0, nullptr);
        // final LN2 of last layer writes the output buffer directly (copy_k removed)
        ln_k<<<BB, 128>>>(p_h, (l == LL - 1) ? out : p_h,
                          p_x, p_x + (size_t)BB * 512,
                          ln2g + l * 512, ln2b + l * 512, p_actH);
    }
}

// round 17
// speedup vs baseline: 1.2214x; 1.0130x over previous
#include <cuda_runtime.h>
#include <cuda_fp16.h>
#include <cstdint>

#define BB 2048
#define NN 64
#define DD 512
#define HH 8
#define LL 3
#define FFD 2048
#define RR 400
#define EE 100000

// ---------------- device scratch ----------------
__device__ __align__(256) __half g_embeH[EE * 512];        // used-rows (compact) fp16 emb_e
__device__ __align__(256) __half g_eW2H[EE * 512];         // compact eW2 rows
__device__ __align__(256) __half g_embrH[RR * 512];
__device__ __align__(256) __half g_actH[2 * BB * 512];     // [0]=hH, [1]=embqH
__device__ __align__(256) __half g_ctxH[BB * HH * 512];
__device__ __align__(256) __half g_ffH[BB * 2048];
__device__ __align__(256) __half g_rW1H[RR * 512];
__device__ __align__(256) __half g_KhatH[LL * RR * 512];
__device__ __align__(256) __half g_W2h[512 * 512];
__device__ __align__(256) __half g_W1h[512 * 512];
__device__ __align__(256) __half g_Wcomb[LL * 2 * 512 * 512];  // [l][0]=W0, [l][1]=Wq[l]
__device__ __align__(256) __half g_Wkh[LL * 512 * 512];
__device__ __align__(256) __half g_Wvh[LL * 512 * 512];
__device__ __align__(256) __half g_F1h[LL * 2048 * 512];
__device__ __align__(256) __half g_F2h[LL * 512 * 2048];
__device__ __align__(256) float  g_bias2[LL * 1024];           // [l]: 512 zeros | bq[l]
__device__ __align__(256) float  g_h[BB * 512];
__device__ __align__(256) float  g_hw0qh[2 * BB * 512];        // [0]=hW0, [1]=qh
__device__ __align__(256) float  g_x[2 * BB * 512];
__device__ unsigned char g_flag[EE];
__device__ int g_cnt;
__device__ int g_list[EE];
__device__ int g_remap[EE];

// ---------------- helpers ----------------
__device__ __forceinline__ uint32_t s2u(const void* p) {
    uint32_t a;
    asm("{ .reg .u64 t; cvta.to.shared.u64 t, %1; cvt.u32.u64 %0, t; }" : "=r"(a) : "l"(p));
    return a;
}
__device__ __forceinline__ void cp16(uint32_t d, const void* s) {
    asm volatile("cp.async.cg.shared.global [%0], [%1], 16;" :: "r"(d), "l"(s));
}
__device__ __forceinline__ void cp_commit() { asm volatile("cp.async.commit_group;" ::: "memory"); }
template<int G> __device__ __forceinline__ void cp_wait() {
    asm volatile("cp.async.wait_group %0;" :: "n"(G) : "memory");
}
__device__ __forceinline__ void ldm4(uint32_t& r0, uint32_t& r1, uint32_t& r2, uint32_t& r3, uint32_t a) {
    asm volatile("ldmatrix.sync.aligned.m8n8.x4.shared.b16 {%0,%1,%2,%3}, [%4];"
        : "=r"(r0), "=r"(r1), "=r"(r2), "=r"(r3) : "r"(a));
}
__device__ __forceinline__ void mma_f16(float* c, const uint32_t* a, const uint32_t* b) {
    asm volatile(
        "mma.sync.aligned.m16n8k16.row.col.f32.f16.f16.f32 "
        "{%0,%1,%2,%3}, {%4,%5,%6,%7}, {%8,%9}, {%0,%1,%2,%3};"
        : "+f"(c[0]), "+f"(c[1]), "+f"(c[2]), "+f"(c[3])
        : "r"(a[0]), "r"(a[1]), "r"(a[2]), "r"(a[3]), "r"(b[0]), "r"(b[1]));
}
// SW128: 16B chunk swizzle within 128B rows
__device__ __forceinline__ uint32_t ofs128(int row, int c) {
    return (uint32_t)(row * 128 + ((c ^ (row & 7)) << 4));
}

// ---------------- fp16 HMMA GEMM, BK=64, 3-stage cp.async pipeline ----------------
// BM in {64,128}: 64 doubles CTA count for skinny-M launches (fills the 296 CTA slots).
template<int BM, int BN, int OUTH>
__global__ void __launch_bounds__(256, 2) gemm_f2(
    const __half* __restrict__ A, int a_ld, long long za,
    const int* __restrict__ gidx, int M,
    const __half* __restrict__ B, long long zb, int K,
    const float* __restrict__ bias, long long zbias,
    void* __restrict__ Cv, int ldc, int zn, long long zc,
    int kz, int kspan, int act, const int* __restrict__ Mdyn)
{
    constexpr int WARPS_N = BN / 32;
    constexpr int WARPS_M = 8 / WARPS_N;
    constexpr int WM = BM / WARPS_M;
    constexpr int MAT_M = WM / 16;
    constexpr int STAGE = (BM + BN) * 128;
    constexpr int UNITS = (BM + BN) * 8;

    extern __shared__ __align__(1024) char smem[];
    int* s_idx = (int*)smem;
    const uint32_t sb = s2u(smem);
    const int tid = threadIdx.x, w = tid >> 5, lane = tid & 31;
    const int wm = w / WARPS_N, wn = w % WARPS_N;
    const int gm0 = blockIdx.y * BM;
    const int bn0 = blockIdx.x * BN;
    const int z = blockIdx.z;
    const int n0g = bn0 + z * zn;

    if (Mdyn) M = *Mdyn;
    if (gm0 >= M) return;

    A += (size_t)z * za;
    B += (size_t)z * zb;
    if (kz && z > 0) bias = nullptr;
    else if (bias) bias += (size_t)z * zbias;

    if (tid < BM) {
        int gr = gm0 + tid;
        if (gr >= M) gr = M - 1;
        s_idx[tid] = gidx ? gidx[gr] : gr;
    }
    __syncthreads();

    const int NCH = K >> 6;
    const int kbeg = kz ? z * kspan : 0;
    const int kcnt = kz ? kspan : NCH;

    auto load_chunk = [&](int c) {
        int s = c % 3;
        int koff = c * 64;
        uint32_t st = sb + 512 + s * STAGE;
#pragma unroll
        for (int it = 0; it < UNITS / 256; it++) {
            int u = tid + it * 256;
            if (u < BM * 8) {
                int r = u >> 3, c16 = u & 7;
                cp16(st + ofs128(r, c16),
                     A + (size_t)s_idx[r] * a_ld + koff + c16 * 8);
            } else {
                int v = u - BM * 8;
                int n = v >> 3, c16 = v & 7;
                cp16(st + BM * 128 + ofs128(n, c16),
                     B + (size_t)(bn0 + n) * K + koff + c16 * 8);
            }
        }
        cp_commit();
    };

    float acc[MAT_M][4][4];
#pragma unroll
    for (int i = 0; i < MAT_M; i++)
#pragma unroll
        for (int j = 0; j < 4; j++)
#pragma unroll
            for (int q = 0; q < 4; q++) acc[i][j][q] = 0.f;

    load_chunk(kbeg);
    load_chunk(kbeg + 1);

    const int r8 = lane & 7, sel = lane >> 3;

    for (int cc = 0; cc < kcnt; cc++) {
        int c = kbeg + cc;
        cp_wait<1>();
        __syncthreads();
        uint32_t stA = sb + 512 + (c % 3) * STAGE;
        uint32_t stB = stA + BM * 128;
#pragma unroll
        for (int kt = 0; kt < 4; kt++) {
            uint32_t a[MAT_M][4];
#pragma unroll
            for (int i = 0; i < MAT_M; i++) {
                int ar = wm * WM + i * 16 + r8 + (sel & 1) * 8;
                int ac = kt * 2 + (sel >> 1);
                ldm4(a[i][0], a[i][1], a[i][2], a[i][3], stA + ofs128(ar, ac));
            }
            uint32_t b[4][2];
#pragma unroll
            for (int p = 0; p < 2; p++) {
                int br = wn * 32 + p * 16 + r8 + (sel >> 1) * 8;
                int bc = kt * 2 + (sel & 1);
                uint32_t t0, t1, t2, t3;
                ldm4(t0, t1, t2, t3, stB + ofs128(br, bc));
                b[2 * p][0] = t0; b[2 * p][1] = t1;
                b[2 * p + 1][0] = t2; b[2 * p + 1][1] = t3;
            }
#pragma unroll
            for (int i = 0; i < MAT_M; i++)
#pragma unroll
                for (int j = 0; j < 4; j++)
                    mma_f16(acc[i][j], a[i], b[j]);
        }
        if (cc + 2 < kcnt) load_chunk(c + 2);
        else cp_commit();
    }

    const int g = lane >> 2, tig = lane & 3;
#pragma unroll
    for (int i = 0; i < MAT_M; i++) {
#pragma unroll
        for (int half = 0; half < 2; half++) {
            int m = gm0 + wm * WM + i * 16 + g + half * 8;
            if (m < M) {
#pragma unroll
                for (int j = 0; j < 4; j++) {
                    int nc = n0g + wn * 32 + j * 8 + tig * 2;
                    float v0 = acc[i][j][half * 2 + 0];
                    float v1 = acc[i][j][half * 2 + 1];
                    if (bias) { v0 += bias[nc]; v1 += bias[nc + 1]; }
                    if (act)  { v0 = fmaxf(v0, 0.f); v1 = fmaxf(v1, 0.f); }
                    if (OUTH) {
                        __half* Ch = (__half*)Cv + (size_t)z * zc;
                        *(__half2*)&Ch[(size_t)m * ldc + nc] = __floats2half2_rn(v0, v1);
                    } else {
                        float* Cf = (float*)Cv + (size_t)z * zc;
                        float2 o; o.x = v0; o.y = v1;
                        *(float2*)&Cf[(size_t)m * ldc + nc] = o;
                    }
                }
            }
        }
    }
}

// ---------------- compaction of used entity rows ----------------
__global__ void __launch_bounds__(256) zero_k(unsigned char* flag, int* cnt)
{
    int i = blockIdx.x * 256 + threadIdx.x;
    if (i < EE) flag[i] = 0;
    if (i == 0) *cnt = 0;
}
__global__ void __launch_bounds__(256) mark_k(const int* __restrict__ nbe, unsigned char* flag)
{
    int i = blockIdx.x * 256 + threadIdx.x;
    if (i < BB * NN) flag[nbe[i]] = 1;
}
__global__ void __launch_bounds__(256) compact_k(
    const unsigned char* __restrict__ flag, int* cnt, int* list, int* remap)
{
    int e = blockIdx.x * 256 + threadIdx.x;
    if (e < EE && flag[e]) {
        int p = atomicAdd(cnt, 1);
        list[p] = e;
        remap[e] = p;
    }
}
// one block per compact row: fully coalesced float4 gather + half2 store
__global__ void __launch_bounds__(128) convGather_k(
    const float* __restrict__ emb_e, const int* __restrict__ list,
    const int* __restrict__ cnt, __half* __restrict__ dst)
{
    int row = blockIdx.x;
    if (row >= *cnt) return;
    const float4* s = (const float4*)(emb_e + (size_t)list[row] * 512);
    float4 v = s[threadIdx.x];
    __half2 a = __floats2half2_rn(v.x, v.y);
    __half2 b = __floats2half2_rn(v.z, v.w);
    uint2 o;
    o.x = *(uint32_t*)&a;
    o.y = *(uint32_t*)&b;
    *(uint2*)(dst + (size_t)row * 512 + threadIdx.x * 4) = o;
}

// ---------------- coalesced transpose weight conversion ----------------
__global__ void __launch_bounds__(256) convT_k(
    const float* __restrict__ W, int str_k, int str_h, long long wmat,
    int K, __half* __restrict__ B2, long long bmat)
{
    __shared__ float t[64][66];
    W += (size_t)blockIdx.z * wmat;
    B2 += (size_t)blockIdx.z * bmat;
    const int k0 = blockIdx.x * 64, n0 = blockIdx.y * 64;
    const float* Wp = W + (size_t)(n0 >> 6) * str_h;
    const int c = threadIdx.x & 63;
    const int r0 = threadIdx.x >> 6;
#pragma unroll
    for (int i = 0; i < 16; i++) {
        int r = r0 + i * 4;
        t[c][r] = Wp[(size_t)(k0 + r) * str_k + c];
    }
    __syncthreads();
    const int ck = threadIdx.x & 31;
    const int rn0 = threadIdx.x >> 5;
#pragma unroll
    for (int i = 0; i < 8; i++) {
        int rn = rn0 + i * 8;
        float2 f = *(const float2*)&t[rn][ck * 2];
        *(__half2*)&B2[(size_t)(n0 + rn) * K + k0 + ck * 2] = __floats2half2_rn(f.x, f.y);
    }
}

__global__ void __launch_bounds__(128) convA_h(
    const float* __restrict__ src, __half* __restrict__ dst)
{
    size_t i = (size_t)blockIdx.x * 512 + threadIdx.x;
#pragma unroll
    for (int t = 0; t < 4; t++)
        dst[i + t * 128] = __float2half_rn(src[i + t * 128]);
}

__global__ void __launch_bounds__(256) biasfill_k(
    const float* __restrict__ bq, float* __restrict__ bias2)
{
    int l = blockIdx.x;
    for (int t = threadIdx.x; t < 1024; t += 256)
        bias2[l * 1024 + t] = (t < 512) ? 0.f : bq[l * 512 + t - 512];
}

// ---------------- fused attention v3: 4-stage prefetch, single sync per iter ----------------
__global__ void __launch_bounds__(256) attn_k(
    const float* __restrict__ qh, const __half* __restrict__ KhatH,
    const int* __restrict__ nbr_r, const int* __restrict__ nbr_e,
    const int* __restrict__ remap,
    const float* __restrict__ masks,
    const float* __restrict__ hW0, const __half* __restrict__ eW2,
    const __half* __restrict__ rW1H,
    __half* __restrict__ ctxH)
{
    const int b = blockIdx.x;
    const int tid = threadIdx.x;
    const int lane = tid & 31, w = tid >> 5;

    __shared__ float s_q[512];
    __shared__ float s_attn[HH * 64];
    __shared__ int   s_nbr[NN], s_nbe[NN], s_act[NN];
    __shared__ int   s_wc[2];
    __shared__ unsigned s_kb[2];
    __shared__ __align__(16) __half s_val[4][1024];   // [stage]: eW2 row | rW1 row

    s_q[tid]       = qh[(size_t)b * 512 + tid];
    s_q[tid + 256] = qh[(size_t)b * 512 + tid + 256];
    s_attn[tid] = -1e31f; s_attn[tid + 256] = -1e31f;
    if (tid < NN) {
        s_nbr[tid] = nbr_r[b * NN + tid];
        s_nbe[tid] = remap[nbr_e[b * NN + tid]];
    }
    if (w < 2) {
        bool keep = masks[b * NN + tid] > 0.5f;
        unsigned bal = __ballot_sync(0xffffffffu, keep);
        if (lane == 0) { s_wc[w] = __popc(bal); s_kb[w] = bal; }
    }
    __syncthreads();
    if (w < 2) {
        unsigned bal = s_kb[w];
        if ((bal >> lane) & 1u) {
            int rank = __popc(bal & ((1u << lane) - 1u)) + (w ? s_wc[0] : 0);
            s_act[rank] = tid;
        }
    }
    const int nact = s_wc[0] + s_wc[1];
    __syncthreads();

    // scores over active neighbors only (Khat fp16, half2 loads)
    {
        float q0 = s_q[w * 64 + 2 * lane], q1 = s_q[w * 64 + 2 * lane + 1];
#pragma unroll 2
        for (int idx = 0; idx < nact; idx++) {
            int n = s_act[idx];
            const __half* kr = KhatH + (size_t)s_nbr[n] * 512 + w * 64;
            float2 kf = __half22float2(*(const __half2*)&kr[2 * lane]);
            float p = q0 * kf.x + q1 * kf.y;
#pragma unroll
            for (int o = 16; o; o >>= 1) p += __shfl_xor_sync(0xffffffffu, p, o);
            if (lane == 0) s_attn[w * 64 + n] = p * 0.125f;
        }
    }
    __syncwarp();
    {
        float s0 = s_attn[w * 64 + lane], s1 = s_attn[w * 64 + lane + 32];
        float m = fmaxf(s0, s1);
#pragma unroll
        for (int o = 16; o; o >>= 1) m = fmaxf(m, __shfl_xor_sync(0xffffffffu, m, o));
        float e0 = expf(s0 - m), e1 = expf(s1 - m);
        float sum = e0 + e1;
#pragma unroll
        for (int o = 16; o; o >>= 1) sum += __shfl_xor_sync(0xffffffffu, sum, o);
        float inv = 1.f / sum;
        s_attn[w * 64 + lane]      = e0 * inv;
        s_attn[w * 64 + lane + 32] = e1 * inv;
    }
    __syncthreads();

    // value pass: 4-stage cp.async prefetch (distance 3) -> single barrier per iteration.
    auto prefetch = [&](int ii) {
        if (ii < nact && tid < 128) {
            int n = s_act[ii];
            int s = ii & 3;
            if (tid < 64)
                cp16(s2u(&s_val[s][tid * 8]), eW2 + (size_t)s_nbe[n] * 512 + tid * 8);
            else
                cp16(s2u(&s_val[s][512 + (tid - 64) * 8]),
                     rW1H + (size_t)s_nbr[n] * 512 + (tid - 64) * 8);
        }
        cp_commit();
    };
    prefetch(0); prefetch(1); prefetch(2);

    const float2 hw0v = *(const float2*)&hW0[(size_t)b * 512 + 2 * tid];
    float acc[HH][2];
#pragma unroll
    for (int hh = 0; hh < HH; hh++) { acc[hh][0] = 0.f; acc[hh][1] = 0.f; }

    for (int ii = 0; ii < nact; ii++) {
        cp_wait<2>();
        __syncthreads();
        int s = ii & 3, n = s_act[ii];
        float2 ev = __half22float2(*(const __half2*)&s_val[s][2 * tid]);
        float2 rv = __half22float2(*(const __half2*)&s_val[s][512 + 2 * tid]);
        float v0 = hw0v.x + ev.x + rv.x;
        float v1 = hw0v.y + ev.y + rv.y;
        v0 = (v0 > 0.f) ? v0 : 0.01f * v0;
        v1 = (v1 > 0.f) ? v1 : 0.01f * v1;
#pragma unroll
        for (int hh = 0; hh < HH; hh++) {
            float a = s_attn[hh * 64 + n];
            acc[hh][0] += a * v0;
            acc[hh][1] += a * v1;
        }
        prefetch(ii + 3);
    }
#pragma unroll
    for (int hh = 0; hh < HH; hh++) {
        *(__half2*)&ctxH[((size_t)b * HH + hh) * 512 + 2 * tid] =
            __floats2half2_rn(acc[hh][0], acc[hh][1]);
    }
}

// ---------------- layernorm (split in/out) ----------------
__global__ void __launch_bounds__(128) ln_k(
    const float* __restrict__ hin, float* __restrict__ hout,
    const float* __restrict__ x, const float* __restrict__ x2,
    const float* __restrict__ gamma, const float* __restrict__ beta,
    __half* __restrict__ hH)
{
    const int b = blockIdx.x, tid = threadIdx.x;
    __shared__ float sred[8];
    float4 hv = ((const float4*)(hin + (size_t)b * 512))[tid];
    float4 xv = ((const float4*)(x + (size_t)b * 512))[tid];
    float v0 = hv.x + xv.x, v1 = hv.y + xv.y, v2 = hv.z + xv.z, v3 = hv.w + xv.w;
    if (x2) {
        float4 x2v = ((const float4*)(x2 + (size_t)b * 512))[tid];
        v0 += x2v.x; v1 += x2v.y; v2 += x2v.z; v3 += x2v.w;
    }

    float s = v0 + v1 + v2 + v3;
#pragma unroll
    for (int o = 16; o; o >>= 1) s += __shfl_xor_sync(0xffffffffu, s, o);
    if ((tid & 31) == 0) sred[tid >> 5] = s;
    __syncthreads();
    float mean = (sred[0] + sred[1] + sred[2] + sred[3]) * (1.f / 512.f);

    v0 -= mean; v1 -= mean; v2 -= mean; v3 -= mean;
    float sq = v0 * v0 + v1 * v1 + v2 * v2 + v3 * v3;
#pragma unroll
    for (int o = 16; o; o >>= 1) sq += __shfl_xor_sync(0xffffffffu, sq, o);
    if ((tid & 31) == 0) sred[4 + (tid >> 5)] = sq;
    __syncthreads();
    float var = (sred[4] + sred[5] + sred[6] + sred[7]) * (1.f / 512.f);
    float rstd = rsqrtf(var + 1e-5f);

    float4 g = ((const float4*)gamma)[tid];
    float4 be = ((const float4*)beta)[tid];
    float o0 = v0 * rstd * g.x + be.x;
    float o1 = v1 * rstd * g.y + be.y;
    float o2 = v2 * rstd * g.z + be.z;
    float o3 = v3 * rstd * g.w + be.w;
    float4 o; o.x = o0; o.y = o1; o.z = o2; o.w = o3;
    ((float4*)(hout + (size_t)b * 512))[tid] = o;

    __half2* d = (__half2*)(hH + (size_t)b * 512 + tid * 4);
    d[0] = __floats2half2_rn(o0, o1);
    d[1] = __floats2half2_rn(o2, o3);
}

// ---------------- init ----------------
__global__ void __launch_bounds__(128) init_k(
    const int* __restrict__ e1, const int* __restrict__ qi,
    const float* __restrict__ emb_e, const float* __restrict__ emb_r,
    float* __restrict__ h, __half* __restrict__ actH,
    float* __restrict__ outq, int writeq)
{
    const int b = blockIdx.x, t = threadIdx.x;
    const float* se = emb_e + (size_t)e1[b] * 512;
    const float* sr = emb_r + (size_t)qi[b] * 512;
    for (int j = t; j < 512; j += 128) {
        float hv = se[j];
        h[(size_t)b * 512 + j] = hv;
        actH[(size_t)b * 512 + j] = __float2half_rn(hv);
        float q = sr[j];
        actH[(size_t)(BB + b) * 512 + j] = __float2half_rn(q);
        if (writeq) outq[(size_t)b * 512 + j] = q;
    }
}

// ---------------- launch ----------------
extern "C" void kernel_launch(void* const* d_in, const int* in_sizes, int n_in,
                              void* d_out, int out_size)
{
    const int*   e1    = (const int*)d_in[0];
    const int*   qidx  = (const int*)d_in[1];
    const int*   nbr_r = (const int*)d_in[2];
    const int*   nbr_e = (const int*)d_in[3];
    const float* masks = (const float*)d_in[4];
    const float* emb_e = (const float*)d_in[5];
    const float* emb_r = (const float*)d_in[6];
    const float* msg_W = (const float*)d_in[7];
    const float* msg_b = (const float*)d_in[8];
    const float* Wq    = (const float*)d_in[9];
    const float* bq    = (const float*)d_in[10];
    const float* Wk    = (const float*)d_in[11];
    const float* bk    = (const float*)d_in[12];
    const float* Wv    = (const float*)d_in[13];
    const float* bv    = (const float*)d_in[14];
    const float* ffW1  = (const float*)d_in[15];
    const float* ffb1  = (const float*)d_in[16];
    const float* ffW2  = (const float*)d_in[17];
    const float* ffb2  = (const float*)d_in[18];
    const float* ln1g  = (const float*)d_in[19];
    const float* ln1b  = (const float*)d_in[20];
    const float* ln2g  = (const float*)d_in[21];
    const float* ln2b  = (const float*)d_in[22];
    float* out = (float*)d_out;

    __half *p_embeH, *p_eW2H, *p_embrH, *p_actH, *p_ctxH, *p_ffH, *p_rW1H, *p_KhatH;
    __half *p_W2h, *p_W1h, *p_Wcomb, *p_Wkh, *p_Wvh, *p_F1h, *p_F2h;
    float *p_bias2, *p_h, *p_hw0qh, *p_x;
    unsigned char* p_flag; int *p_cnt, *p_list, *p_remap;
    cudaGetSymbolAddress((void**)&p_embeH, g_embeH);
    cudaGetSymbolAddress((void**)&p_eW2H,  g_eW2H);
    cudaGetSymbolAddress((void**)&p_embrH, g_embrH);
    cudaGetSymbolAddress((void**)&p_actH,  g_actH);
    cudaGetSymbolAddress((void**)&p_ctxH,  g_ctxH);
    cudaGetSymbolAddress((void**)&p_ffH,   g_ffH);
    cudaGetSymbolAddress((void**)&p_rW1H,  g_rW1H);
    cudaGetSymbolAddress((void**)&p_KhatH, g_KhatH);
    cudaGetSymbolAddress((void**)&p_W2h,   g_W2h);
    cudaGetSymbolAddress((void**)&p_W1h,   g_W1h);
    cudaGetSymbolAddress((void**)&p_Wcomb, g_Wcomb);
    cudaGetSymbolAddress((void**)&p_Wkh,   g_Wkh);
    cudaGetSymbolAddress((void**)&p_Wvh,   g_Wvh);
    cudaGetSymbolAddress((void**)&p_F1h,   g_F1h);
    cudaGetSymbolAddress((void**)&p_F2h,   g_F2h);
    cudaGetSymbolAddress((void**)&p_bias2, g_bias2);
    cudaGetSymbolAddress((void**)&p_h,     g_h);
    cudaGetSymbolAddress((void**)&p_hw0qh, g_hw0qh);
    cudaGetSymbolAddress((void**)&p_x,     g_x);
    cudaGetSymbolAddress((void**)&p_flag,  g_flag);
    cudaGetSymbolAddress((void**)&p_cnt,   g_cnt);
    cudaGetSymbolAddress((void**)&p_list,  g_list);
    cudaGetSymbolAddress((void**)&p_remap, g_remap);

    const int SM128_128 = 512 + 3 * ((128 + 128) * 128);  // 98816
    const int SM64_128  = 512 + 3 * ((64 + 128) * 128);   // 74240
    const int SM64_64   = 512 + 3 * ((64 + 64) * 128);    // 49664
    cudaFuncSetAttribute((gemm_f2<128, 128, 1>), cudaFuncAttributeMaxDynamicSharedMemorySize, SM128_128);
    cudaFuncSetAttribute((gemm_f2<64, 128, 1>),  cudaFuncAttributeMaxDynamicSharedMemorySize, SM64_128);
    cudaFuncSetAttribute((gemm_f2<64, 128, 0>),  cudaFuncAttributeMaxDynamicSharedMemorySize, SM64_128);
    cudaFuncSetAttribute((gemm_f2<64, 64, 0>),   cudaFuncAttributeMaxDynamicSharedMemorySize, SM64_64);

    int writeq = (out_size >= 2 * BB * DD) ? 1 : 0;

    // used-row compaction
    zero_k<<<(EE + 255) / 256, 256>>>(p_flag, p_cnt);
    mark_k<<<(BB * NN + 255) / 256, 256>>>(nbr_e, p_flag);
    compact_k<<<(EE + 255) / 256, 256>>>(p_flag, p_cnt, p_list, p_remap);
    convGather_k<<<EE, 128>>>(emb_e, p_list, p_cnt, p_embeH);
    convT_k<<<dim3(8, 8, 1), 256>>>(msg_W + 1024 * 512, 512, 64, 0, 512, p_W2h, 0);
    // eW2 = used_rows(emb_e) @ W2 + msg_b (compact M)
    gemm_f2<128, 128, 1><<<dim3(4, (EE + 127) / 128), 256, SM128_128>>>(
        p_embeH, 512, 0, nullptr, EE, p_W2h, 0, 512,
        msg_b, 0, p_eW2H, 512, 0, 0, 0, 0, 0, p_cnt);

    init_k<<<BB, 128>>>(e1, qidx, emb_e, emb_r, p_h, p_actH, out + (size_t)BB * DD, writeq);
    convT_k<<<dim3(8, 8, 1), 256>>>(msg_W + 512 * 512, 512, 64, 0, 512, p_W1h, 0);
    convA_h<<<RR, 128>>>(emb_r, p_embrH);
    biasfill_k<<<LL, 256>>>(bq, p_bias2);
    convT_k<<<dim3(8, 8, LL), 256>>>(msg_W, 512, 64, 0, 512, p_Wcomb, 524288);
    convT_k<<<dim3(8, 8, LL), 256>>>(Wq, 64, 32768, 262144, 512, p_Wcomb + 262144, 524288);
    convT_k<<<dim3(8, 8, LL), 256>>>(Wk, 64, 32768, 262144, 512, p_Wkh, 262144);
    convT_k<<<dim3(8, 8, LL), 256>>>(Wv, 64, 32768, 262144, 512, p_Wvh, 262144);
    convT_k<<<dim3(8, 32, LL), 256>>>(ffW1, 2048, 64, 1048576, 512, p_F1h, 1048576);
    convT_k<<<dim3(32, 8, LL), 256>>>(ffW2, 512, 64, 1048576, 2048, p_F2h, 1048576);

    // rW1H = half(emb_r @ W1)
    gemm_f2<64, 128, 1><<<dim3(4, 7), 256, SM64_128>>>(
        p_embrH, 512, 0, nullptr, RR, p_W1h, 0, 512,
        nullptr, 0, p_rW1H, 512, 0, 0, 0, 0, 0, nullptr);
    // KhatH[l] = half(emb_r @ Wk[l] + bk[l])
    gemm_f2<64, 128, 1><<<dim3(4, 7, LL), 256, SM64_128>>>(
        p_embrH, 512, 0, nullptr, RR, p_Wkh, 262144, 512,
        bk, 512, p_KhatH, 512, 0, (long long)RR * 512, 0, 0, 0, nullptr);

    for (int l = 0; l < LL; l++) {
        // z=0: hW0 = h @ W0; z=1: qh = embq @ Wq[l] + bq[l]  (BM=64 -> 256 CTAs)
        gemm_f2<64, 128, 0><<<dim3(4, 32, 2), 256, SM64_128>>>(
            p_actH, 512, (long long)BB * 512, nullptr, BB,
            p_Wcomb + (size_t)l * 2 * 262144, 262144, 512,
            p_bias2 + l * 1024, 512,
            p_hw0qh, 512, 0, (long long)BB * 512, 0, 0, 0, nullptr);
        attn_k<<<BB, 256>>>(p_hw0qh + (size_t)BB * 512, p_KhatH + (size_t)l * RR * 512,
                            nbr_r, nbr_e, p_remap, masks, p_hw0qh, p_eW2H, p_rW1H, p_ctxH);
        // x = ctx @ Wv[l] + bv[l] (z = head; BM=64 -> 256 CTAs)
        gemm_f2<64, 64, 0><<<dim3(1, 32, 8), 256, SM64_64>>>(
            p_ctxH, 4096, 512, nullptr, BB,
            p_Wvh + (size_t)l * 262144, 32768, 512,
            bv + l * 512, 0, p_x, 512, 64, 0, 0, 0, 0, nullptr);
        ln_k<<<BB, 128>>>(p_h, p_h, p_x, nullptr, ln1g + l * 512, ln1b + l * 512, p_actH);
        // ffH = fp16(relu(h @ F1 + b1))
        gemm_f2<128, 128, 1><<<dim3(16, 16), 256, SM128_128>>>(
            p_actH, 512, 0, nullptr, BB,
            p_F1h + (size_t)l * 1048576, 0, 512,
            ffb1 + l * 2048, 0, p_ffH, 2048, 0, 0, 0, 0, 1, nullptr);
        // x0/x1 = split-K halves of ff @ F2 (+ b2 on z=0; BM=64 -> 256 CTAs)
        gemm_f2<64, 128, 0><<<dim3(4, 32, 2), 256, SM64_128>>>(
            p_ffH, 2048, 0, nullptr, BB,
            p_F2h + (size_t)l * 1048576, 0, 2048,
            ffb2 + l * 512, 0, p_x, 512, 0, (long long)BB * 512, 1, 16, 0, nullptr);
        // final LN2 of last layer writes the output buffer directly
        ln_k<<<BB, 128>>>(p_h, (l == LL - 1) ? out : p_h,
                          p_x, p_x + (size_t)BB * 512,
                          ln2g + l * 512, ln2b + l * 512, p_actH);
    }
}